// round 13
// baseline (speedup 1.0000x reference)
#include <cuda_runtime.h>
#include <cuda_bf16.h>
#include <math.h>
#include <stdint.h>

// Problem constants
#define D_MODEL 1024
#define D_INNER 2048
#define D_STATE 16
#define DT_RANK 64
#define D_CONV  4
#define BB      2
#define LL      1024
#define BL      (BB * LL)                 // 2048 tokens
#define KS      16                        // split-K for x_proj
#define NCH     32                        // scan chunks per sequence
#define CHL     (LL / NCH)                // 32 steps per chunk

// ---------------------------------------------------------------------------
// Device scratch. 3-segment K-concat split (K' = 3K), fully materialized:
//   act-style: [hi | lo | hi], wt-style: [hi | hi | lo]
// Transposed dataflow: xzT/xcT/deltaT/yT are [channel][token].
// ---------------------------------------------------------------------------
__device__ float          g_xzT[4096 * BL];
__device__ float          g_xcT[D_INNER * BL];
__device__ __nv_bfloat16  g_xcs[BL * 6144];
__device__ float          g_xpart[KS * BL * 128];
__device__ float          g_xdbl[BL * 128];
__device__ __nv_bfloat16  g_dtA[BL * 192];
__device__ float          g_deltaT[D_INNER * BL];
__device__ float          g_yT[D_INNER * BL];
__device__ __nv_bfloat16  g_ys[BL * 6144];
__device__ __nv_bfloat16  g_xs[BL * 3072];
__device__ __nv_bfloat16  g_wi[4096 * 3072];
__device__ __nv_bfloat16  g_wo[1024 * 6144];
__device__ __nv_bfloat16  g_wx[128 * 6144];
__device__ __nv_bfloat16  g_wdt[2048 * 192];
__device__ float          g_opart[2 * BL * D_MODEL];

// ---------------------------------------------------------------------------
// helpers
// ---------------------------------------------------------------------------
__device__ __forceinline__ void cvt_pair(float x, float y,
                                         uint32_t& hi, uint32_t& lo) {
    asm("cvt.rn.bf16x2.f32 %0, %1, %2;" : "=r"(hi) : "f"(y), "f"(x));
    const float hx = __uint_as_float(hi << 16);
    const float hy = __uint_as_float(hi & 0xFFFF0000u);
    asm("cvt.rn.bf16x2.f32 %0, %1, %2;" : "=r"(lo) : "f"(y - hy), "f"(x - hx));
}

__device__ __forceinline__ void cp16(uint32_t s, const void* g) {
    asm volatile("cp.async.cg.shared.global [%0], [%1], 16;" :: "r"(s), "l"(g));
}
__device__ __forceinline__ void cp_commit() {
    asm volatile("cp.async.commit_group;");
}
__device__ __forceinline__ void cp_wait1() {
    asm volatile("cp.async.wait_group 1;" ::: "memory");
}

#define LDSM_X4(r0, r1, r2, r3, addr) \
    asm volatile("ldmatrix.sync.aligned.m8n8.x4.shared.b16 {%0,%1,%2,%3}, [%4];" \
                 : "=r"(r0), "=r"(r1), "=r"(r2), "=r"(r3) : "r"(addr))

__device__ __forceinline__ void mma_bf16(float (&c)[4],
                                         uint32_t a0, uint32_t a1,
                                         uint32_t a2, uint32_t a3,
                                         uint32_t b0, uint32_t b1) {
    asm volatile(
        "mma.sync.aligned.m16n8k16.row.col.f32.bf16.bf16.f32 "
        "{%0,%1,%2,%3},{%4,%5,%6,%7},{%8,%9},{%0,%1,%2,%3};"
        : "+f"(c[0]), "+f"(c[1]), "+f"(c[2]), "+f"(c[3])
        : "r"(a0), "r"(a1), "r"(a2), "r"(a3), "r"(b0), "r"(b1));
}

// ---------------------------------------------------------------------------
// bf16 HGEMM (pre-split operands), BM=BN=128, BK=64, 512 thr, 3-stage ring.
// EPI==1: +bias[col], softplus.  EPI==2: +bias[row], softplus (swapped GEMMs).
// Split-K via blockIdx.z. Requires M%128==0, N%128==0, K'%64==0/split, T>=2.
// (R11-exact inner loop: branch-free, strength-reducible address chains.)
// ---------------------------------------------------------------------------
template<int EPI>
__global__ void __launch_bounds__(512, 2)
hgemm(const __nv_bfloat16* __restrict__ A, const __nv_bfloat16* __restrict__ W,
      float* __restrict__ C, int lda, int ldw, int ldc, int T,
      long czstride, const float* __restrict__ bias)
{
    constexpr int S = 3;
    extern __shared__ __align__(16) char smem[];
    const uint32_t smA0 = (uint32_t)__cvta_generic_to_shared(smem);
    const uint32_t smB0 = smA0 + S * 16384;

    const int tid  = threadIdx.x;
    const int wid  = tid >> 5;
    const int lane = tid & 31;
    const int wm   = wid >> 2;
    const int wn   = wid & 3;
    const int l16  = lane & 15;
    const int chal = lane >> 4;

    const long blockM = (long)blockIdx.y * 128;
    const long blockN = (long)blockIdx.x * 128;
    const int  koff   = blockIdx.z * T * 64;

    const __nv_bfloat16* Ab = A + blockM * lda + koff;
    const __nv_bfloat16* Wb = W + blockN * ldw + koff;

    const int crow = tid >> 3;
    const int ccc  = tid & 7;

    uint32_t aoff[2], asw[2], boff[2], bsw[2];
#pragma unroll
    for (int mi = 0; mi < 2; mi++) {
        const int r = wm * 32 + mi * 16 + l16;
        aoff[mi] = r * 128;
        asw[mi]  = r & 7;
    }
#pragma unroll
    for (int ni = 0; ni < 2; ni++) {
        const int r = wn * 32 + ni * 16 + l16;
        boff[ni] = r * 128;
        bsw[ni]  = r & 7;
    }

    float acc[2][4][4];
#pragma unroll
    for (int mi = 0; mi < 2; mi++)
#pragma unroll
        for (int n8 = 0; n8 < 4; n8++)
#pragma unroll
            for (int j = 0; j < 4; j++) acc[mi][n8][j] = 0.f;

    auto issue = [&](int s, int t) {
        const int k0 = t * 64;
        const uint32_t dA = smA0 + s * 16384;
        const uint32_t dB = smB0 + s * 16384;
#pragma unroll
        for (int p = 0; p < 2; p++) {
            const int row = crow + p * 64;
            const int scc = ccc ^ (row & 7);
            cp16(dA + row * 128 + scc * 16, Ab + (long)row * lda + k0 + ccc * 8);
            cp16(dB + row * 128 + scc * 16, Wb + (long)row * ldw + k0 + ccc * 8);
        }
    };

    issue(0, 0);
    cp_commit();
    issue(1, 1);
    cp_commit();

    for (int t = 0; t < T; t++) {
        cp_wait1();
        __syncthreads();
        const int nt = t + 2;
        if (nt < T) issue(nt % S, nt);
        cp_commit();

        const uint32_t sA = smA0 + (t % S) * 16384;
        const uint32_t sB = smB0 + (t % S) * 16384;
#pragma unroll
        for (int k16 = 0; k16 < 4; k16++) {
            const uint32_t ch = (uint32_t)(k16 * 2 + chal);
            uint32_t a[2][4], b[2][4];
#pragma unroll
            for (int mi = 0; mi < 2; mi++)
                LDSM_X4(a[mi][0], a[mi][1], a[mi][2], a[mi][3],
                        sA + aoff[mi] + ((ch ^ asw[mi]) << 4));
#pragma unroll
            for (int ni = 0; ni < 2; ni++)
                LDSM_X4(b[ni][0], b[ni][1], b[ni][2], b[ni][3],
                        sB + boff[ni] + ((ch ^ bsw[ni]) << 4));
#pragma unroll
            for (int mi = 0; mi < 2; mi++)
#pragma unroll
                for (int n8 = 0; n8 < 4; n8++) {
                    const int np = n8 >> 1;
                    const uint32_t b0 = (n8 & 1) ? b[np][1] : b[np][0];
                    const uint32_t b1 = (n8 & 1) ? b[np][3] : b[np][2];
                    mma_bf16(acc[mi][n8],
                             a[mi][0], a[mi][1], a[mi][2], a[mi][3], b0, b1);
                }
        }
    }

    float* Cb = C + (long)blockIdx.z * czstride;
    const int er = lane >> 2;
    const int ec = (lane & 3) * 2;
#pragma unroll
    for (int mi = 0; mi < 2; mi++) {
#pragma unroll
        for (int n8 = 0; n8 < 4; n8++) {
            const long row = blockM + wm * 32 + mi * 16 + er;
            const int  col = (int)blockN + wn * 32 + n8 * 8 + ec;
            float v0 = acc[mi][n8][0], v1 = acc[mi][n8][1];
            float v2 = acc[mi][n8][2], v3 = acc[mi][n8][3];
            if (EPI == 2) {
                const float br = bias[row], br8 = bias[row + 8];
                v0 += br; v1 += br; v2 += br8; v3 += br8;
                v0 = (v0 > 20.f) ? v0 : log1pf(expf(v0));
                v1 = (v1 > 20.f) ? v1 : log1pf(expf(v1));
                v2 = (v2 > 20.f) ? v2 : log1pf(expf(v2));
                v3 = (v3 > 20.f) ? v3 : log1pf(expf(v3));
            }
            *(float2*)&Cb[row * ldc + col]       = make_float2(v0, v1);
            *(float2*)&Cb[(row + 8) * ldc + col] = make_float2(v2, v3);
        }
    }
}

// ---------------------------------------------------------------------------
// f32 -> bf16 3-segment split core (materialized, row stride 3K)
// ---------------------------------------------------------------------------
__device__ __forceinline__ void split_body(const float* __restrict__ in,
                                           __nv_bfloat16* __restrict__ out,
                                           int K, int li, int inRows, int act)
{
    const int e   = li * 4;
    const int row = e / K;
    const int k   = e - row * K;
    float4 v = make_float4(0.f, 0.f, 0.f, 0.f);
    if (row < inRows) v = *(const float4*)(in + (long)row * K + k);
    uint32_t h01, l01, h23, l23;
    cvt_pair(v.x, v.y, h01, l01);
    cvt_pair(v.z, v.w, h23, l23);
    __nv_bfloat16* o = out + (long)row * 3 * K + k;
    const uint2 hv = make_uint2(h01, h23);
    const uint2 lv = make_uint2(l01, l23);
    if (act) {
        *(uint2*)o           = hv;
        *(uint2*)(o + K)     = lv;
        *(uint2*)(o + 2 * K) = hv;
    } else {
        *(uint2*)o           = hv;
        *(uint2*)(o + K)     = hv;
        *(uint2*)(o + 2 * K) = lv;
    }
}

#define N4_X   (BL * 1024 / 4)
#define N4_WI  (4096 * 1024 / 4)
#define N4_WO  (1024 * 2048 / 4)
#define N4_WX  (128 * 2048 / 4)
#define N4_WDT (2048 * 64 / 4)
__global__ void split_all(const float* __restrict__ x_in,
                          const float* __restrict__ wi_in,
                          const float* __restrict__ wo_in,
                          const float* __restrict__ wx_in,
                          const float* __restrict__ wdt_in,
                          __nv_bfloat16* __restrict__ xs,
                          __nv_bfloat16* __restrict__ wi,
                          __nv_bfloat16* __restrict__ wo,
                          __nv_bfloat16* __restrict__ wx,
                          __nv_bfloat16* __restrict__ wdt)
{
    int i = blockIdx.x * 256 + threadIdx.x;
    if (i < N4_X) { split_body(x_in, xs, 1024, i, BL, 1); return; }
    i -= N4_X;
    if (i < N4_WI) { split_body(wi_in, wi, 1024, i, 4096, 0); return; }
    i -= N4_WI;
    if (i < N4_WO) { split_body(wo_in, wo, 2048, i, 1024, 0); return; }
    i -= N4_WO;
    if (i < N4_WX) { split_body(wx_in, wx, 2048, i, 96, 0); return; }
    i -= N4_WX;
    if (i < N4_WDT) { split_body(wdt_in, wdt, 64, i, 2048, 0); }
}
#define N4_ALL (N4_X + N4_WI + N4_WO + N4_WX + N4_WDT)

// ---------------------------------------------------------------------------
// Split-K reduce for x_proj partials + dt-row act-split (row 192)
// ---------------------------------------------------------------------------
__global__ void reduce_split(const float* __restrict__ p,
                             float* __restrict__ xdbl,
                             __nv_bfloat16* __restrict__ dtA)
{
    const int n4 = BL * 128 / 4;
    const int i = blockIdx.x * 256 + threadIdx.x;
    if (i >= n4) return;
    float4 a = ((const float4*)p)[i];
#pragma unroll
    for (int s = 1; s < KS; s++) {
        const float4 b = ((const float4*)p)[(long)s * n4 + i];
        a.x += b.x; a.y += b.y; a.z += b.z; a.w += b.w;
    }
    ((float4*)xdbl)[i] = a;
    const int e = i * 4;
    const int col = e & 127;
    if (col < 64) {
        const int row = e >> 7;
        uint32_t h01, l01, h23, l23;
        cvt_pair(a.x, a.y, h01, l01);
        cvt_pair(a.z, a.w, h23, l23);
        __nv_bfloat16* o = dtA + (long)row * 192 + col;
        const uint2 hv = make_uint2(h01, h23);
        *(uint2*)o         = hv;
        *(uint2*)(o + 64)  = make_uint2(l01, l23);
        *(uint2*)(o + 128) = hv;
    }
}

// ---------------------------------------------------------------------------
// Depthwise causal conv (k=4) + bias + SiLU in transposed layout, fused with
// 3-seg act-split transpose: writes xcT [d][token] f32 AND xcs [token][6144].
// ---------------------------------------------------------------------------
__global__ void conv_split_T(const float* __restrict__ xzT,
                             const float* __restrict__ cw,
                             const float* __restrict__ cb,
                             float* __restrict__ xcT,
                             __nv_bfloat16* __restrict__ xcs)
{
    __shared__ float tile[32][33];
    const int d0 = blockIdx.x * 32;
    const int r0 = blockIdx.y * 32;
    const int tx = threadIdx.x;

#pragma unroll
    for (int i = threadIdx.y; i < 32; i += 8) {
        const int d  = d0 + i;
        const int tt = r0 + tx;
        const int l  = tt & (LL - 1);
        const float* row = xzT + ((long)d << 11);
        float acc = cb[d];
#pragma unroll
        for (int k = 0; k < D_CONV; k++) {
            const int ll = l - (D_CONV - 1) + k;
            if (ll >= 0)
                acc = fmaf(row[tt - (D_CONV - 1) + k], cw[d * D_CONV + k], acc);
        }
        const float s = acc / (1.f + __expf(-acc));
        xcT[((long)d << 11) + tt] = s;
        tile[i][tx] = s;
    }
    __syncthreads();
#pragma unroll
    for (int i = threadIdx.y; i < 32; i += 8) {
        const float v = tile[tx][i];
        const int row = r0 + i;
        const int d   = d0 + tx;
        const __nv_bfloat16 hh = __float2bfloat16(v);
        __nv_bfloat16* o = xcs + (long)row * 6144 + d;
        o[0]    = hh;
        o[2048] = __float2bfloat16(v - __bfloat162float(hh));
        o[4096] = hh;
    }
}

// ---------------------------------------------------------------------------
// [d][token] f32 -> [token][6144] 3-seg act-split (yT -> ys)
// ---------------------------------------------------------------------------
__global__ void splitT(const float* __restrict__ src,
                       __nv_bfloat16* __restrict__ dst)
{
    __shared__ float tile[32][33];
    const int d0 = blockIdx.x * 32;
    const int r0 = blockIdx.y * 32;
#pragma unroll
    for (int i = threadIdx.y; i < 32; i += 8)
        tile[i][threadIdx.x] = src[(long)(d0 + i) * BL + r0 + threadIdx.x];
    __syncthreads();
#pragma unroll
    for (int i = threadIdx.y; i < 32; i += 8) {
        const float v = tile[threadIdx.x][i];
        const int row = r0 + i;
        const int d   = d0 + threadIdx.x;
        const __nv_bfloat16 hh = __float2bfloat16(v);
        __nv_bfloat16* o = dst + (long)row * 6144 + d;
        o[0]    = hh;
        o[2048] = __float2bfloat16(v - __bfloat162float(hh));
        o[4096] = hh;
    }
}

// ---------------------------------------------------------------------------
// FUSED chunked selective scan: one block per (b, d).
// 512 threads = 32 chunks x 16 states. 3 phases:
//   1) local chunk scans from h=0 -> S,P in smem
//   2) 16 threads do the 32-chunk prefix -> Hc in smem
//   3) rescan seeded with Hc, shfl-reduce over states, gated yT write
// ---------------------------------------------------------------------------
__global__ void __launch_bounds__(512)
scan_fused(const float* __restrict__ dtT,
           const float* __restrict__ xcT,
           const float* __restrict__ zT,
           const float* __restrict__ xdbl,
           const float* __restrict__ A_log,
           const float* __restrict__ Dv,
           float* __restrict__ yT)
{
    __shared__ float Ssm[NCH * 16];
    __shared__ float Psm[NCH * 16];
    __shared__ float Hsm[NCH * 16];

    const int tid = threadIdx.x;
    const int n   = tid & 15;
    const int c   = tid >> 4;           // chunk 0..31
    const int d   = blockIdx.x & (D_INNER - 1);
    const int b   = blockIdx.x >> 11;

    const float Aval = -__expf(A_log[d * D_STATE + n]);
    const float Dd   = Dv[d];

    const long base = ((long)d << 11) + (b << 10) + c * CHL;
    const float4* dp4 = (const float4*)(dtT + base);
    const float4* xp4 = (const float4*)(xcT + base);
    const float4* zp4 = (const float4*)(zT + base);
    const float* xdp  = xdbl + ((long)b * LL + c * CHL) * 128 + 64 + n;
    float* yp = yT + base;

    // ---- phase 1: local scan from 0 ----
    {
        float h = 0.f, Pr = 1.f;
#pragma unroll
        for (int q = 0; q < CHL / 4; q++) {
            const float4 dl4 = dp4[q];
            const float4 xc4 = xp4[q];
#pragma unroll
            for (int j = 0; j < 4; j++) {
                const float dl  = (j == 0) ? dl4.x : (j == 1) ? dl4.y : (j == 2) ? dl4.z : dl4.w;
                const float xcv = (j == 0) ? xc4.x : (j == 1) ? xc4.y : (j == 2) ? xc4.z : xc4.w;
                const float Bv  = xdp[(q * 4 + j) * 128];
                const float a   = __expf(dl * Aval);
                Pr *= a;
                h = fmaf(a, h, dl * Bv * xcv);
            }
        }
        Ssm[c * 16 + n] = h;
        Psm[c * 16 + n] = Pr;
    }
    __syncthreads();

    // ---- phase 2: chunk prefix (16 threads, one per state) ----
    if (tid < 16) {
        float H = 0.f;
#pragma unroll
        for (int cc = 0; cc < NCH; cc++) {
            Hsm[cc * 16 + tid] = H;
            H = fmaf(Psm[cc * 16 + tid], H, Ssm[cc * 16 + tid]);
        }
    }
    __syncthreads();

    // ---- phase 3: seeded rescan + output ----
    float h = Hsm[c * 16 + n];
#pragma unroll
    for (int q = 0; q < CHL / 4; q++) {
        const float4 dl4 = dp4[q];
        const float4 xc4 = xp4[q];
        const float4 zv4 = zp4[q];
#pragma unroll
        for (int j = 0; j < 4; j++) {
            const float dl  = (j == 0) ? dl4.x : (j == 1) ? dl4.y : (j == 2) ? dl4.z : dl4.w;
            const float xcv = (j == 0) ? xc4.x : (j == 1) ? xc4.y : (j == 2) ? xc4.z : xc4.w;
            const float zv  = (j == 0) ? zv4.x : (j == 1) ? zv4.y : (j == 2) ? zv4.z : zv4.w;
            const float Bv  = xdp[(q * 4 + j) * 128];
            const float Cv  = xdp[(q * 4 + j) * 128 + 16];

            const float a = __expf(dl * Aval);
            h = fmaf(a, h, dl * Bv * xcv);

            float p = h * Cv;
            p += __shfl_xor_sync(0xffffffffu, p, 8);
            p += __shfl_xor_sync(0xffffffffu, p, 4);
            p += __shfl_xor_sync(0xffffffffu, p, 2);
            p += __shfl_xor_sync(0xffffffffu, p, 1);

            if (n == 0) {
                const float sig = 1.f / (1.f + __expf(-zv));
                yp[q * 4 + j] = (p + xcv * Dd) * (zv * sig);
            }
        }
    }
}

// ---------------------------------------------------------------------------
// out_proj split-K=2 final reduce
// ---------------------------------------------------------------------------
__global__ void reduce_out(const float* __restrict__ p, float* __restrict__ o)
{
    const int n4 = BL * D_MODEL / 4;
    const int i = blockIdx.x * 256 + threadIdx.x;
    if (i >= n4) return;
    const float4 a = ((const float4*)p)[i];
    const float4 b = ((const float4*)p)[n4 + i];
    ((float4*)o)[i] = make_float4(a.x + b.x, a.y + b.y, a.z + b.z, a.w + b.w);
}

// ---------------------------------------------------------------------------
// Launch
// ---------------------------------------------------------------------------
extern "C" void kernel_launch(void* const* d_in, const int* in_sizes, int n_in,
                              void* d_out, int out_size)
{
    const float* x         = (const float*)d_in[0];
    const float* in_proj_w = (const float*)d_in[1];
    const float* conv_w    = (const float*)d_in[2];
    const float* conv_b    = (const float*)d_in[3];
    const float* x_proj_w  = (const float*)d_in[4];
    const float* dt_proj_w = (const float*)d_in[5];
    const float* dt_proj_b = (const float*)d_in[6];
    const float* A_log     = (const float*)d_in[7];
    const float* Dv        = (const float*)d_in[8];
    const float* out_proj  = (const float*)d_in[9];
    float* out = (float*)d_out;

    float *xzT, *xcT, *xpart, *xdbl, *deltaT, *yT, *opart;
    __nv_bfloat16 *xcs, *dtA, *ys, *xs, *wi, *wo, *wx, *wdt;
    cudaGetSymbolAddress((void**)&xzT,    g_xzT);
    cudaGetSymbolAddress((void**)&xcT,    g_xcT);
    cudaGetSymbolAddress((void**)&xcs,    g_xcs);
    cudaGetSymbolAddress((void**)&xpart,  g_xpart);
    cudaGetSymbolAddress((void**)&xdbl,   g_xdbl);
    cudaGetSymbolAddress((void**)&dtA,    g_dtA);
    cudaGetSymbolAddress((void**)&deltaT, g_deltaT);
    cudaGetSymbolAddress((void**)&yT,     g_yT);
    cudaGetSymbolAddress((void**)&ys,     g_ys);
    cudaGetSymbolAddress((void**)&xs,     g_xs);
    cudaGetSymbolAddress((void**)&wi,     g_wi);
    cudaGetSymbolAddress((void**)&wo,     g_wo);
    cudaGetSymbolAddress((void**)&wx,     g_wx);
    cudaGetSymbolAddress((void**)&wdt,    g_wdt);
    cudaGetSymbolAddress((void**)&opart,  g_opart);

    const int SMEM_SZ = 6 * 16384;   // 96 KB -> 2 CTAs/SM
    static bool attr_set = false;
    if (!attr_set) {
        cudaFuncSetAttribute(hgemm<0>, cudaFuncAttributeMaxDynamicSharedMemorySize, SMEM_SZ);
        cudaFuncSetAttribute(hgemm<2>, cudaFuncAttributeMaxDynamicSharedMemorySize, SMEM_SZ);
        attr_set = true;
    }

    // launch 0: all operand splits (3-seg materialized)
    split_all<<<(N4_ALL + 255) / 256, 256>>>(
        x, in_proj_w, out_proj, x_proj_w, dt_proj_w, xs, wi, wo, wx, wdt);

    // launch 1: xzT = in_proj_w @ x.T  (M=4096 ch, N=2048 tok, K'=3072)
    hgemm<0><<<dim3(16, 32, 1), 512, SMEM_SZ>>>(
        wi, xs, xzT, 3072, 3072, BL, 48, 0, nullptr);

    // launch 2: conv + silu + act-split (xcT f32 and xcs bf16)
    conv_split_T<<<dim3(64, 64), dim3(32, 8)>>>(xzT, conv_w, conv_b, xcT, xcs);

    // launch 3: x_dbl = xc @ x_proj_w.T (split-K=16)
    hgemm<0><<<dim3(1, 16, KS), 512, SMEM_SZ>>>(
        xcs, wx, xpart, 6144, 6144, 128, 6144 / KS / 64, (long)BL * 128, nullptr);
    // launch 4: reduce + dt act-split
    reduce_split<<<(BL * 128 / 4 + 255) / 256, 256>>>(xpart, xdbl, dtA);

    // launch 5: deltaT = softplus(dt_proj_w @ dt.T + b)
    hgemm<2><<<dim3(16, 16, 1), 512, SMEM_SZ>>>(
        wdt, dtA, deltaT, 192, 192, BL, 3, 0, dt_proj_b);

    // launch 6: fused chunked selective scan
    scan_fused<<<BB * D_INNER, 512>>>(
        deltaT, xcT, xzT + (long)2048 * BL, xdbl, A_log, Dv, yT);

    // launch 7: yT -> ys (act-split for out_proj)
    splitT<<<dim3(64, 64), dim3(32, 8)>>>(yT, ys);

    // launch 8-9: out = y @ out_proj_w.T (split-K=2) + reduce
    hgemm<0><<<dim3(8, 16, 2), 512, SMEM_SZ>>>(
        ys, wo, opart, 6144, 6144, 1024, 48, (long)BL * D_MODEL, nullptr);
    reduce_out<<<(BL * D_MODEL / 4 + 255) / 256, 256>>>(opart, out);
}

// round 14
// speedup vs baseline: 1.1200x; 1.1200x over previous
#include <cuda_runtime.h>
#include <cuda_bf16.h>
#include <math.h>
#include <stdint.h>

// Problem constants
#define D_MODEL 1024
#define D_INNER 2048
#define D_STATE 16
#define DT_RANK 64
#define D_CONV  4
#define BB      2
#define LL      1024
#define BL      (BB * LL)                 // 2048 tokens
#define KS      16                        // split-K for x_proj
#define NCH     64                        // scan chunks per sequence
#define CHL     (LL / NCH)                // 16 steps per chunk

// ---------------------------------------------------------------------------
// Device scratch. 3-segment K-concat split (K' = 3K), fully materialized:
//   act-style: [hi | lo | hi], wt-style: [hi | hi | lo]
// Transposed dataflow: xzT/xcT/deltaT/yT are [channel][token].
// ---------------------------------------------------------------------------
__device__ float          g_xzT[4096 * BL];
__device__ float          g_xcT[D_INNER * BL];
__device__ __nv_bfloat16  g_xcs[BL * 6144];
__device__ float          g_xpart[KS * BL * 128];
__device__ float          g_xdbl[BL * 128];
__device__ __nv_bfloat16  g_dtA[BL * 192];
__device__ float          g_deltaT[D_INNER * BL];
__device__ float          g_yT[D_INNER * BL];
__device__ __nv_bfloat16  g_ys[BL * 6144];
__device__ __nv_bfloat16  g_xs[BL * 3072];
__device__ __nv_bfloat16  g_wi[4096 * 3072];
__device__ __nv_bfloat16  g_wo[1024 * 6144];
__device__ __nv_bfloat16  g_wx[128 * 6144];
__device__ __nv_bfloat16  g_wdt[2048 * 192];
// chunked-scan intermediates, t = ((b*NCH+c)*D_INNER+d)*16+n
__device__ float          g_S[BB * NCH * D_INNER * D_STATE];
__device__ float          g_P[BB * NCH * D_INNER * D_STATE];
__device__ float          g_Hc[BB * NCH * D_INNER * D_STATE];
// out_proj split-K partials
__device__ float          g_opart[2 * BL * D_MODEL];

// ---------------------------------------------------------------------------
// helpers
// ---------------------------------------------------------------------------
__device__ __forceinline__ void cvt_pair(float x, float y,
                                         uint32_t& hi, uint32_t& lo) {
    asm("cvt.rn.bf16x2.f32 %0, %1, %2;" : "=r"(hi) : "f"(y), "f"(x));
    const float hx = __uint_as_float(hi << 16);
    const float hy = __uint_as_float(hi & 0xFFFF0000u);
    asm("cvt.rn.bf16x2.f32 %0, %1, %2;" : "=r"(lo) : "f"(y - hy), "f"(x - hx));
}

__device__ __forceinline__ void cp16(uint32_t s, const void* g) {
    asm volatile("cp.async.cg.shared.global [%0], [%1], 16;" :: "r"(s), "l"(g));
}
__device__ __forceinline__ void cp_commit() {
    asm volatile("cp.async.commit_group;");
}
__device__ __forceinline__ void cp_wait1() {
    asm volatile("cp.async.wait_group 1;" ::: "memory");
}

#define LDSM_X4(r0, r1, r2, r3, addr) \
    asm volatile("ldmatrix.sync.aligned.m8n8.x4.shared.b16 {%0,%1,%2,%3}, [%4];" \
                 : "=r"(r0), "=r"(r1), "=r"(r2), "=r"(r3) : "r"(addr))

__device__ __forceinline__ void mma_bf16(float (&c)[4],
                                         uint32_t a0, uint32_t a1,
                                         uint32_t a2, uint32_t a3,
                                         uint32_t b0, uint32_t b1) {
    asm volatile(
        "mma.sync.aligned.m16n8k16.row.col.f32.bf16.bf16.f32 "
        "{%0,%1,%2,%3},{%4,%5,%6,%7},{%8,%9},{%0,%1,%2,%3};"
        : "+f"(c[0]), "+f"(c[1]), "+f"(c[2]), "+f"(c[3])
        : "r"(a0), "r"(a1), "r"(a2), "r"(a3), "r"(b0), "r"(b1));
}

// ---------------------------------------------------------------------------
// bf16 HGEMM (pre-split operands), BM=BN=128, BK=64, 512 thr, 3-stage ring.
// EPI==1: +bias[col], softplus.  EPI==2: +bias[row], softplus (swapped GEMMs).
// Split-K via blockIdx.z. Requires M%128==0, N%128==0, K'%64==0/split, T>=2.
// ---------------------------------------------------------------------------
template<int EPI>
__global__ void __launch_bounds__(512, 2)
hgemm(const __nv_bfloat16* __restrict__ A, const __nv_bfloat16* __restrict__ W,
      float* __restrict__ C, int lda, int ldw, int ldc, int T,
      long czstride, const float* __restrict__ bias)
{
    constexpr int S = 3;
    extern __shared__ __align__(16) char smem[];
    const uint32_t smA0 = (uint32_t)__cvta_generic_to_shared(smem);
    const uint32_t smB0 = smA0 + S * 16384;

    const int tid  = threadIdx.x;
    const int wid  = tid >> 5;
    const int lane = tid & 31;
    const int wm   = wid >> 2;
    const int wn   = wid & 3;
    const int l16  = lane & 15;
    const int chal = lane >> 4;

    const long blockM = (long)blockIdx.y * 128;
    const long blockN = (long)blockIdx.x * 128;
    const int  koff   = blockIdx.z * T * 64;

    const __nv_bfloat16* Ab = A + blockM * lda + koff;
    const __nv_bfloat16* Wb = W + blockN * ldw + koff;

    const int crow = tid >> 3;
    const int ccc  = tid & 7;

    uint32_t aoff[2], asw[2], boff[2], bsw[2];
#pragma unroll
    for (int mi = 0; mi < 2; mi++) {
        const int r = wm * 32 + mi * 16 + l16;
        aoff[mi] = r * 128;
        asw[mi]  = r & 7;
    }
#pragma unroll
    for (int ni = 0; ni < 2; ni++) {
        const int r = wn * 32 + ni * 16 + l16;
        boff[ni] = r * 128;
        bsw[ni]  = r & 7;
    }

    float acc[2][4][4];
#pragma unroll
    for (int mi = 0; mi < 2; mi++)
#pragma unroll
        for (int n8 = 0; n8 < 4; n8++)
#pragma unroll
            for (int j = 0; j < 4; j++) acc[mi][n8][j] = 0.f;

    auto issue = [&](int s, int t) {
        const int k0 = t * 64;
        const uint32_t dA = smA0 + s * 16384;
        const uint32_t dB = smB0 + s * 16384;
#pragma unroll
        for (int p = 0; p < 2; p++) {
            const int row = crow + p * 64;
            const int scc = ccc ^ (row & 7);
            cp16(dA + row * 128 + scc * 16, Ab + (long)row * lda + k0 + ccc * 8);
            cp16(dB + row * 128 + scc * 16, Wb + (long)row * ldw + k0 + ccc * 8);
        }
    };

    issue(0, 0);
    cp_commit();
    issue(1, 1);
    cp_commit();

    for (int t = 0; t < T; t++) {
        cp_wait1();
        __syncthreads();
        const int nt = t + 2;
        if (nt < T) issue(nt % S, nt);
        cp_commit();

        const uint32_t sA = smA0 + (t % S) * 16384;
        const uint32_t sB = smB0 + (t % S) * 16384;
#pragma unroll
        for (int k16 = 0; k16 < 4; k16++) {
            const uint32_t ch = (uint32_t)(k16 * 2 + chal);
            uint32_t a[2][4], b[2][4];
#pragma unroll
            for (int mi = 0; mi < 2; mi++)
                LDSM_X4(a[mi][0], a[mi][1], a[mi][2], a[mi][3],
                        sA + aoff[mi] + ((ch ^ asw[mi]) << 4));
#pragma unroll
            for (int ni = 0; ni < 2; ni++)
                LDSM_X4(b[ni][0], b[ni][1], b[ni][2], b[ni][3],
                        sB + boff[ni] + ((ch ^ bsw[ni]) << 4));
#pragma unroll
            for (int mi = 0; mi < 2; mi++)
#pragma unroll
                for (int n8 = 0; n8 < 4; n8++) {
                    const int np = n8 >> 1;
                    const uint32_t b0 = (n8 & 1) ? b[np][1] : b[np][0];
                    const uint32_t b1 = (n8 & 1) ? b[np][3] : b[np][2];
                    mma_bf16(acc[mi][n8],
                             a[mi][0], a[mi][1], a[mi][2], a[mi][3], b0, b1);
                }
        }
    }

    float* Cb = C + (long)blockIdx.z * czstride;
    const int er = lane >> 2;
    const int ec = (lane & 3) * 2;
#pragma unroll
    for (int mi = 0; mi < 2; mi++) {
#pragma unroll
        for (int n8 = 0; n8 < 4; n8++) {
            const long row = blockM + wm * 32 + mi * 16 + er;
            const int  col = (int)blockN + wn * 32 + n8 * 8 + ec;
            float v0 = acc[mi][n8][0], v1 = acc[mi][n8][1];
            float v2 = acc[mi][n8][2], v3 = acc[mi][n8][3];
            if (EPI == 1) {
                const float b0 = bias[col], b1 = bias[col + 1];
                v0 += b0; v1 += b1; v2 += b0; v3 += b1;
                v0 = (v0 > 20.f) ? v0 : log1pf(expf(v0));
                v1 = (v1 > 20.f) ? v1 : log1pf(expf(v1));
                v2 = (v2 > 20.f) ? v2 : log1pf(expf(v2));
                v3 = (v3 > 20.f) ? v3 : log1pf(expf(v3));
            } else if (EPI == 2) {
                const float br = bias[row], br8 = bias[row + 8];
                v0 += br; v1 += br; v2 += br8; v3 += br8;
                v0 = (v0 > 20.f) ? v0 : log1pf(expf(v0));
                v1 = (v1 > 20.f) ? v1 : log1pf(expf(v1));
                v2 = (v2 > 20.f) ? v2 : log1pf(expf(v2));
                v3 = (v3 > 20.f) ? v3 : log1pf(expf(v3));
            }
            *(float2*)&Cb[row * ldc + col]       = make_float2(v0, v1);
            *(float2*)&Cb[(row + 8) * ldc + col] = make_float2(v2, v3);
        }
    }
}

// ---------------------------------------------------------------------------
// f32 -> bf16 3-segment split core
// ---------------------------------------------------------------------------
__device__ __forceinline__ void split_body(const float* __restrict__ in,
                                           __nv_bfloat16* __restrict__ out,
                                           int K, int li, int inRows, int act)
{
    const int e   = li * 4;
    const int row = e / K;
    const int k   = e - row * K;
    float4 v = make_float4(0.f, 0.f, 0.f, 0.f);
    if (row < inRows) v = *(const float4*)(in + (long)row * K + k);
    uint32_t h01, l01, h23, l23;
    cvt_pair(v.x, v.y, h01, l01);
    cvt_pair(v.z, v.w, h23, l23);
    __nv_bfloat16* o = out + (long)row * 3 * K + k;
    const uint2 hv = make_uint2(h01, h23);
    const uint2 lv = make_uint2(l01, l23);
    if (act) {
        *(uint2*)o           = hv;
        *(uint2*)(o + K)     = lv;
        *(uint2*)(o + 2 * K) = hv;
    } else {
        *(uint2*)o           = hv;
        *(uint2*)(o + K)     = hv;
        *(uint2*)(o + 2 * K) = lv;
    }
}

#define N4_X   (BL * 1024 / 4)
#define N4_WI  (4096 * 1024 / 4)
#define N4_WO  (1024 * 2048 / 4)
#define N4_WX  (128 * 2048 / 4)
#define N4_WDT (2048 * 64 / 4)
__global__ void split_all(const float* __restrict__ x_in,
                          const float* __restrict__ wi_in,
                          const float* __restrict__ wo_in,
                          const float* __restrict__ wx_in,
                          const float* __restrict__ wdt_in,
                          __nv_bfloat16* __restrict__ xs,
                          __nv_bfloat16* __restrict__ wi,
                          __nv_bfloat16* __restrict__ wo,
                          __nv_bfloat16* __restrict__ wx,
                          __nv_bfloat16* __restrict__ wdt)
{
    int i = blockIdx.x * 256 + threadIdx.x;
    if (i < N4_X) { split_body(x_in, xs, 1024, i, BL, 1); return; }
    i -= N4_X;
    if (i < N4_WI) { split_body(wi_in, wi, 1024, i, 4096, 0); return; }
    i -= N4_WI;
    if (i < N4_WO) { split_body(wo_in, wo, 2048, i, 1024, 0); return; }
    i -= N4_WO;
    if (i < N4_WX) { split_body(wx_in, wx, 2048, i, 96, 0); return; }
    i -= N4_WX;
    if (i < N4_WDT) { split_body(wdt_in, wdt, 64, i, 2048, 0); }
}
#define N4_ALL (N4_X + N4_WI + N4_WO + N4_WX + N4_WDT)

// ---------------------------------------------------------------------------
// Split-K reduce for x_proj partials + dt-row act-split
// ---------------------------------------------------------------------------
__global__ void reduce_split(const float* __restrict__ p,
                             float* __restrict__ xdbl,
                             __nv_bfloat16* __restrict__ dtA)
{
    const int n4 = BL * 128 / 4;
    const int i = blockIdx.x * 256 + threadIdx.x;
    if (i >= n4) return;
    float4 a = ((const float4*)p)[i];
#pragma unroll
    for (int s = 1; s < KS; s++) {
        const float4 b = ((const float4*)p)[(long)s * n4 + i];
        a.x += b.x; a.y += b.y; a.z += b.z; a.w += b.w;
    }
    ((float4*)xdbl)[i] = a;
    const int e = i * 4;
    const int col = e & 127;
    if (col < 64) {
        const int row = e >> 7;
        uint32_t h01, l01, h23, l23;
        cvt_pair(a.x, a.y, h01, l01);
        cvt_pair(a.z, a.w, h23, l23);
        __nv_bfloat16* o = dtA + (long)row * 192 + col;
        const uint2 hv = make_uint2(h01, h23);
        *(uint2*)o         = hv;
        *(uint2*)(o + 64)  = make_uint2(l01, l23);
        *(uint2*)(o + 128) = hv;
    }
}

// ---------------------------------------------------------------------------
// Depthwise causal conv (k=4) + bias + SiLU in transposed layout, fused with
// 3-seg act-split transpose: writes xcT [d][token] f32 AND xcs [token][6144].
// ---------------------------------------------------------------------------
__global__ void conv_split_T(const float* __restrict__ xzT,
                             const float* __restrict__ cw,
                             const float* __restrict__ cb,
                             float* __restrict__ xcT,
                             __nv_bfloat16* __restrict__ xcs)
{
    __shared__ float tile[32][33];
    const int d0 = blockIdx.x * 32;
    const int r0 = blockIdx.y * 32;
    const int tx = threadIdx.x;

#pragma unroll
    for (int i = threadIdx.y; i < 32; i += 8) {
        const int d  = d0 + i;
        const int tt = r0 + tx;
        const int l  = tt & (LL - 1);
        const float* row = xzT + ((long)d << 11);
        float acc = cb[d];
#pragma unroll
        for (int k = 0; k < D_CONV; k++) {
            const int ll = l - (D_CONV - 1) + k;
            if (ll >= 0)
                acc = fmaf(row[tt - (D_CONV - 1) + k], cw[d * D_CONV + k], acc);
        }
        const float s = acc / (1.f + __expf(-acc));
        xcT[((long)d << 11) + tt] = s;
        tile[i][tx] = s;
    }
    __syncthreads();
#pragma unroll
    for (int i = threadIdx.y; i < 32; i += 8) {
        const float v = tile[tx][i];
        const int row = r0 + i;
        const int d   = d0 + tx;
        const __nv_bfloat16 hh = __float2bfloat16(v);
        __nv_bfloat16* o = xcs + (long)row * 6144 + d;
        o[0]    = hh;
        o[2048] = __float2bfloat16(v - __bfloat162float(hh));
        o[4096] = hh;
    }
}

// ---------------------------------------------------------------------------
// [d][token] f32 -> [token][6144] 3-seg act-split (yT -> ys)
// ---------------------------------------------------------------------------
__global__ void splitT(const float* __restrict__ src,
                       __nv_bfloat16* __restrict__ dst)
{
    __shared__ float tile[32][33];
    const int d0 = blockIdx.x * 32;
    const int r0 = blockIdx.y * 32;
#pragma unroll
    for (int i = threadIdx.y; i < 32; i += 8)
        tile[i][threadIdx.x] = src[(long)(d0 + i) * BL + r0 + threadIdx.x];
    __syncthreads();
#pragma unroll
    for (int i = threadIdx.y; i < 32; i += 8) {
        const float v = tile[threadIdx.x][i];
        const int row = r0 + i;
        const int d   = d0 + threadIdx.x;
        const __nv_bfloat16 hh = __float2bfloat16(v);
        __nv_bfloat16* o = dst + (long)row * 6144 + d;
        o[0]    = hh;
        o[2048] = __float2bfloat16(v - __bfloat162float(hh));
        o[4096] = hh;
    }
}

// ---------------------------------------------------------------------------
// 3-pass chunked selective scan over transposed operands. NCH=64, CHL=16.
// t = ((b*NCH + c)*D_INNER + d)*16 + n ;  c = (g>>11)&63, b = g>>17
// ---------------------------------------------------------------------------
__global__ void scan_pass_a(const float* __restrict__ dtT,
                            const float* __restrict__ xcT,
                            const float* __restrict__ xdbl,
                            const float* __restrict__ A_log,
                            float* __restrict__ Sarr,
                            float* __restrict__ Parr)
{
    const int t = blockIdx.x * 256 + threadIdx.x;
    const int n = t & 15;
    const int g = t >> 4;
    const int d = g & (D_INNER - 1);
    const int c = (g >> 11) & (NCH - 1);
    const int b = g >> 17;

    const float Aval = -__expf(A_log[d * D_STATE + n]);
    const long base = ((long)d << 11) + (b << 10) + c * CHL;
    const float4* dp4 = (const float4*)(dtT + base);
    const float4* xp4 = (const float4*)(xcT + base);
    const float* xdp  = xdbl + ((long)b * LL + c * CHL) * 128 + 64 + n;

    float h = 0.f, Pr = 1.f;
#pragma unroll
    for (int q = 0; q < CHL / 4; q++) {
        const float4 dl4 = dp4[q];
        const float4 xc4 = xp4[q];
#pragma unroll
        for (int j = 0; j < 4; j++) {
            const float dl  = (j == 0) ? dl4.x : (j == 1) ? dl4.y : (j == 2) ? dl4.z : dl4.w;
            const float xcv = (j == 0) ? xc4.x : (j == 1) ? xc4.y : (j == 2) ? xc4.z : xc4.w;
            const float Bv  = xdp[(q * 4 + j) * 128];
            const float a   = __expf(dl * Aval);
            Pr *= a;
            h = fmaf(a, h, dl * Bv * xcv);
        }
    }
    Sarr[t] = h;
    Parr[t] = Pr;
}

__global__ void scan_pass_b(const float* __restrict__ Sarr,
                            const float* __restrict__ Parr,
                            float* __restrict__ Hc)
{
    const int t = blockIdx.x * 256 + threadIdx.x;
    const int n = t & 15;
    const int d = (t >> 4) & (D_INNER - 1);
    const int b = t >> 15;
    float H = 0.f;
#pragma unroll
    for (int c = 0; c < NCH; c++) {
        const long idx = ((long)((b * NCH + c) * D_INNER + d) << 4) + n;
        Hc[idx] = H;
        H = fmaf(Parr[idx], H, Sarr[idx]);
    }
}

__global__ void scan_pass_c(const float* __restrict__ dtT,
                            const float* __restrict__ xcT,
                            const float* __restrict__ zT,
                            const float* __restrict__ xdbl,
                            const float* __restrict__ A_log,
                            const float* __restrict__ Dv,
                            const float* __restrict__ Hc,
                            float* __restrict__ yT)
{
    const int t = blockIdx.x * 256 + threadIdx.x;
    const int n = t & 15;
    const int g = t >> 4;
    const int d = g & (D_INNER - 1);
    const int c = (g >> 11) & (NCH - 1);
    const int b = g >> 17;

    const float Aval = -__expf(A_log[d * D_STATE + n]);
    const float Dd   = Dv[d];

    const long base = ((long)d << 11) + (b << 10) + c * CHL;
    const float4* dp4 = (const float4*)(dtT + base);
    const float4* xp4 = (const float4*)(xcT + base);
    const float4* zp4 = (const float4*)(zT + base);
    const float* xdp  = xdbl + ((long)b * LL + c * CHL) * 128 + 64 + n;
    float* yp = yT + base;

    float h = Hc[t];
#pragma unroll
    for (int q = 0; q < CHL / 4; q++) {
        const float4 dl4 = dp4[q];
        const float4 xc4 = xp4[q];
        const float4 zv4 = zp4[q];
#pragma unroll
        for (int j = 0; j < 4; j++) {
            const float dl  = (j == 0) ? dl4.x : (j == 1) ? dl4.y : (j == 2) ? dl4.z : dl4.w;
            const float xcv = (j == 0) ? xc4.x : (j == 1) ? xc4.y : (j == 2) ? xc4.z : xc4.w;
            const float zv  = (j == 0) ? zv4.x : (j == 1) ? zv4.y : (j == 2) ? zv4.z : zv4.w;
            const float Bv  = xdp[(q * 4 + j) * 128];
            const float Cv  = xdp[(q * 4 + j) * 128 + 16];

            const float a = __expf(dl * Aval);
            h = fmaf(a, h, dl * Bv * xcv);

            float p = h * Cv;
            p += __shfl_xor_sync(0xffffffffu, p, 8);
            p += __shfl_xor_sync(0xffffffffu, p, 4);
            p += __shfl_xor_sync(0xffffffffu, p, 2);
            p += __shfl_xor_sync(0xffffffffu, p, 1);

            if (n == 0) {
                const float sig = 1.f / (1.f + __expf(-zv));
                yp[q * 4 + j] = (p + xcv * Dd) * (zv * sig);
            }
        }
    }
}

// ---------------------------------------------------------------------------
// out_proj split-K=2 final reduce
// ---------------------------------------------------------------------------
__global__ void reduce_out(const float* __restrict__ p, float* __restrict__ o)
{
    const int n4 = BL * D_MODEL / 4;
    const int i = blockIdx.x * 256 + threadIdx.x;
    if (i >= n4) return;
    const float4 a = ((const float4*)p)[i];
    const float4 b = ((const float4*)p)[n4 + i];
    ((float4*)o)[i] = make_float4(a.x + b.x, a.y + b.y, a.z + b.z, a.w + b.w);
}

// ---------------------------------------------------------------------------
// Launch
// ---------------------------------------------------------------------------
extern "C" void kernel_launch(void* const* d_in, const int* in_sizes, int n_in,
                              void* d_out, int out_size)
{
    const float* x         = (const float*)d_in[0];
    const float* in_proj_w = (const float*)d_in[1];
    const float* conv_w    = (const float*)d_in[2];
    const float* conv_b    = (const float*)d_in[3];
    const float* x_proj_w  = (const float*)d_in[4];
    const float* dt_proj_w = (const float*)d_in[5];
    const float* dt_proj_b = (const float*)d_in[6];
    const float* A_log     = (const float*)d_in[7];
    const float* Dv        = (const float*)d_in[8];
    const float* out_proj  = (const float*)d_in[9];
    float* out = (float*)d_out;

    float *xzT, *xcT, *xpart, *xdbl, *deltaT, *yT, *Sarr, *Parr, *Hc, *opart;
    __nv_bfloat16 *xcs, *dtA, *ys, *xs, *wi, *wo, *wx, *wdt;
    cudaGetSymbolAddress((void**)&xzT,    g_xzT);
    cudaGetSymbolAddress((void**)&xcT,    g_xcT);
    cudaGetSymbolAddress((void**)&xcs,    g_xcs);
    cudaGetSymbolAddress((void**)&xpart,  g_xpart);
    cudaGetSymbolAddress((void**)&xdbl,   g_xdbl);
    cudaGetSymbolAddress((void**)&dtA,    g_dtA);
    cudaGetSymbolAddress((void**)&deltaT, g_deltaT);
    cudaGetSymbolAddress((void**)&yT,     g_yT);
    cudaGetSymbolAddress((void**)&ys,     g_ys);
    cudaGetSymbolAddress((void**)&xs,     g_xs);
    cudaGetSymbolAddress((void**)&wi,     g_wi);
    cudaGetSymbolAddress((void**)&wo,     g_wo);
    cudaGetSymbolAddress((void**)&wx,     g_wx);
    cudaGetSymbolAddress((void**)&wdt,    g_wdt);
    cudaGetSymbolAddress((void**)&Sarr,   g_S);
    cudaGetSymbolAddress((void**)&Parr,   g_P);
    cudaGetSymbolAddress((void**)&Hc,     g_Hc);
    cudaGetSymbolAddress((void**)&opart,  g_opart);

    const int SMEM_SZ = 6 * 16384;   // 96 KB -> 2 CTAs/SM
    static bool attr_set = false;
    if (!attr_set) {
        cudaFuncSetAttribute(hgemm<0>, cudaFuncAttributeMaxDynamicSharedMemorySize, SMEM_SZ);
        cudaFuncSetAttribute(hgemm<2>, cudaFuncAttributeMaxDynamicSharedMemorySize, SMEM_SZ);
        attr_set = true;
    }

    // launch 0: all operand splits (3-seg materialized)
    split_all<<<(N4_ALL + 255) / 256, 256>>>(
        x, in_proj_w, out_proj, x_proj_w, dt_proj_w, xs, wi, wo, wx, wdt);

    // launch 1: xzT = in_proj_w @ x.T  (M=4096 ch, N=2048 tok, K'=3072)
    hgemm<0><<<dim3(16, 32, 1), 512, SMEM_SZ>>>(
        wi, xs, xzT, 3072, 3072, BL, 48, 0, nullptr);

    // launch 2: conv + silu + act-split (xcT f32 and xcs bf16)
    conv_split_T<<<dim3(64, 64), dim3(32, 8)>>>(xzT, conv_w, conv_b, xcT, xcs);

    // launch 3: x_dbl = xc @ x_proj_w.T (split-K=16)
    hgemm<0><<<dim3(1, 16, KS), 512, SMEM_SZ>>>(
        xcs, wx, xpart, 6144, 6144, 128, 6144 / KS / 64, (long)BL * 128, nullptr);
    // launch 4: reduce + dt act-split
    reduce_split<<<(BL * 128 / 4 + 255) / 256, 256>>>(xpart, xdbl, dtA);

    // launch 5: deltaT = softplus(dt_proj_w @ dt.T + b)
    hgemm<2><<<dim3(16, 16, 1), 512, SMEM_SZ>>>(
        wdt, dtA, deltaT, 192, 192, BL, 3, 0, dt_proj_b);

    // launch 6-8: 3-pass chunked selective scan (NCH=64)
    scan_pass_a<<<BB * NCH * D_INNER * D_STATE / 256, 256>>>(
        deltaT, xcT, xdbl, A_log, Sarr, Parr);
    scan_pass_b<<<BB * D_INNER * D_STATE / 256, 256>>>(Sarr, Parr, Hc);
    scan_pass_c<<<BB * NCH * D_INNER * D_STATE / 256, 256>>>(
        deltaT, xcT, xzT + (long)2048 * BL, xdbl, A_log, Dv, Hc, yT);

    // launch 9: yT -> ys (act-split for out_proj)
    splitT<<<dim3(64, 64), dim3(32, 8)>>>(yT, ys);

    // launch 10-11: out = y @ out_proj_w.T (split-K=2) + reduce
    hgemm<0><<<dim3(8, 16, 2), 512, SMEM_SZ>>>(
        ys, wo, opart, 6144, 6144, 1024, 48, (long)BL * D_MODEL, nullptr);
    reduce_out<<<(BL * D_MODEL / 4 + 255) / 256, 256>>>(opart, out);
}

// round 15
// speedup vs baseline: 1.5057x; 1.3444x over previous
#include <cuda_runtime.h>
#include <cuda_fp16.h>
#include <math.h>
#include <stdint.h>

// Problem constants
#define D_MODEL 1024
#define D_INNER 2048
#define D_STATE 16
#define DT_RANK 64
#define D_CONV  4
#define BB      2
#define LL      1024
#define BL      (BB * LL)                 // 2048 tokens
#define KS      16                        // split-K for x_proj
#define NCH     32                        // scan chunks per sequence
#define CHL     (LL / NCH)                // 32 steps per chunk

// ---------------------------------------------------------------------------
// Device scratch. fp16 2-segment split (K' = 2K):
//   activations: [hi | lo]  (hi + lo reconstructs f32 to ~2^-22)
//   weights:     [hi | hi]  (hi duplicated)
// => A'.W'^T = (a_hi + a_lo) * w_hi = exact activation x fp16 weight.
// Transposed dataflow: xzT/xcT/deltaT/yT are [channel][token].
// ---------------------------------------------------------------------------
__device__ float   g_xzT[4096 * BL];
__device__ float   g_xcT[D_INNER * BL];
__device__ __half  g_xcs[BL * 4096];
__device__ float   g_xpart[KS * BL * 128];
__device__ float   g_xdbl[BL * 128];
__device__ __half  g_dtA[BL * 128];
__device__ float   g_deltaT[D_INNER * BL];
__device__ float   g_yT[D_INNER * BL];
__device__ __half  g_ys[BL * 4096];
__device__ __half  g_xs[BL * 2048];
__device__ __half  g_wi[4096 * 2048];
__device__ __half  g_wo[1024 * 4096];
__device__ __half  g_wx[128 * 4096];
__device__ __half  g_wdt[2048 * 128];
// chunked-scan intermediates, t = ((b*NCH+c)*D_INNER+d)*16+n
__device__ float   g_S[BB * NCH * D_INNER * D_STATE];
__device__ float   g_P[BB * NCH * D_INNER * D_STATE];
__device__ float   g_Hc[BB * NCH * D_INNER * D_STATE];
// out_proj split-K partials
__device__ float   g_opart[2 * BL * D_MODEL];

// ---------------------------------------------------------------------------
// helpers
// ---------------------------------------------------------------------------
__device__ __forceinline__ void cvt_pair(float x, float y,
                                         uint32_t& hi, uint32_t& lo) {
    // hi = {f16(y) , f16(x)} with x in low half
    asm("cvt.rn.f16x2.f32 %0, %1, %2;" : "=r"(hi) : "f"(y), "f"(x));
    const __half2 h2 = *reinterpret_cast<const __half2*>(&hi);
    const float hx = __low2float(h2);
    const float hy = __high2float(h2);
    asm("cvt.rn.f16x2.f32 %0, %1, %2;" : "=r"(lo) : "f"(y - hy), "f"(x - hx));
}

__device__ __forceinline__ void cp16(uint32_t s, const void* g) {
    asm volatile("cp.async.cg.shared.global [%0], [%1], 16;" :: "r"(s), "l"(g));
}
__device__ __forceinline__ void cp_commit() {
    asm volatile("cp.async.commit_group;");
}
__device__ __forceinline__ void cp_wait1() {
    asm volatile("cp.async.wait_group 1;" ::: "memory");
}

#define LDSM_X4(r0, r1, r2, r3, addr) \
    asm volatile("ldmatrix.sync.aligned.m8n8.x4.shared.b16 {%0,%1,%2,%3}, [%4];" \
                 : "=r"(r0), "=r"(r1), "=r"(r2), "=r"(r3) : "r"(addr))

__device__ __forceinline__ void mma_f16(float (&c)[4],
                                        uint32_t a0, uint32_t a1,
                                        uint32_t a2, uint32_t a3,
                                        uint32_t b0, uint32_t b1) {
    asm volatile(
        "mma.sync.aligned.m16n8k16.row.col.f32.f16.f16.f32 "
        "{%0,%1,%2,%3},{%4,%5,%6,%7},{%8,%9},{%0,%1,%2,%3};"
        : "+f"(c[0]), "+f"(c[1]), "+f"(c[2]), "+f"(c[3])
        : "r"(a0), "r"(a1), "r"(a2), "r"(a3), "r"(b0), "r"(b1));
}

// ---------------------------------------------------------------------------
// fp16 HGEMM (pre-split operands), BM=BN=128, BK=64, 512 thr, 3-stage ring.
// EPI==2: +bias[row], softplus (swapped-output GEMMs).
// Split-K via blockIdx.z. Requires M%128==0, N%128==0, K'%64==0/split, T>=2.
// ---------------------------------------------------------------------------
template<int EPI>
__global__ void __launch_bounds__(512, 2)
hgemm(const __half* __restrict__ A, const __half* __restrict__ W,
      float* __restrict__ C, int lda, int ldw, int ldc, int T,
      long czstride, const float* __restrict__ bias)
{
    constexpr int S = 3;
    extern __shared__ __align__(16) char smem[];
    const uint32_t smA0 = (uint32_t)__cvta_generic_to_shared(smem);
    const uint32_t smB0 = smA0 + S * 16384;

    const int tid  = threadIdx.x;
    const int wid  = tid >> 5;
    const int lane = tid & 31;
    const int wm   = wid >> 2;
    const int wn   = wid & 3;
    const int l16  = lane & 15;
    const int chal = lane >> 4;

    const long blockM = (long)blockIdx.y * 128;
    const long blockN = (long)blockIdx.x * 128;
    const int  koff   = blockIdx.z * T * 64;

    const __half* Ab = A + blockM * lda + koff;
    const __half* Wb = W + blockN * ldw + koff;

    const int crow = tid >> 3;
    const int ccc  = tid & 7;

    uint32_t aoff[2], asw[2], boff[2], bsw[2];
#pragma unroll
    for (int mi = 0; mi < 2; mi++) {
        const int r = wm * 32 + mi * 16 + l16;
        aoff[mi] = r * 128;
        asw[mi]  = r & 7;
    }
#pragma unroll
    for (int ni = 0; ni < 2; ni++) {
        const int r = wn * 32 + ni * 16 + l16;
        boff[ni] = r * 128;
        bsw[ni]  = r & 7;
    }

    float acc[2][4][4];
#pragma unroll
    for (int mi = 0; mi < 2; mi++)
#pragma unroll
        for (int n8 = 0; n8 < 4; n8++)
#pragma unroll
            for (int j = 0; j < 4; j++) acc[mi][n8][j] = 0.f;

    auto issue = [&](int s, int t) {
        const int k0 = t * 64;
        const uint32_t dA = smA0 + s * 16384;
        const uint32_t dB = smB0 + s * 16384;
#pragma unroll
        for (int p = 0; p < 2; p++) {
            const int row = crow + p * 64;
            const int scc = ccc ^ (row & 7);
            cp16(dA + row * 128 + scc * 16, Ab + (long)row * lda + k0 + ccc * 8);
            cp16(dB + row * 128 + scc * 16, Wb + (long)row * ldw + k0 + ccc * 8);
        }
    };

    issue(0, 0);
    cp_commit();
    issue(1, 1);
    cp_commit();

    for (int t = 0; t < T; t++) {
        cp_wait1();
        __syncthreads();
        const int nt = t + 2;
        if (nt < T) issue(nt % S, nt);
        cp_commit();

        const uint32_t sA = smA0 + (t % S) * 16384;
        const uint32_t sB = smB0 + (t % S) * 16384;
#pragma unroll
        for (int k16 = 0; k16 < 4; k16++) {
            const uint32_t ch = (uint32_t)(k16 * 2 + chal);
            uint32_t a[2][4], b[2][4];
#pragma unroll
            for (int mi = 0; mi < 2; mi++)
                LDSM_X4(a[mi][0], a[mi][1], a[mi][2], a[mi][3],
                        sA + aoff[mi] + ((ch ^ asw[mi]) << 4));
#pragma unroll
            for (int ni = 0; ni < 2; ni++)
                LDSM_X4(b[ni][0], b[ni][1], b[ni][2], b[ni][3],
                        sB + boff[ni] + ((ch ^ bsw[ni]) << 4));
#pragma unroll
            for (int mi = 0; mi < 2; mi++)
#pragma unroll
                for (int n8 = 0; n8 < 4; n8++) {
                    const int np = n8 >> 1;
                    const uint32_t b0 = (n8 & 1) ? b[np][1] : b[np][0];
                    const uint32_t b1 = (n8 & 1) ? b[np][3] : b[np][2];
                    mma_f16(acc[mi][n8],
                            a[mi][0], a[mi][1], a[mi][2], a[mi][3], b0, b1);
                }
        }
    }

    float* Cb = C + (long)blockIdx.z * czstride;
    const int er = lane >> 2;
    const int ec = (lane & 3) * 2;
#pragma unroll
    for (int mi = 0; mi < 2; mi++) {
#pragma unroll
        for (int n8 = 0; n8 < 4; n8++) {
            const long row = blockM + wm * 32 + mi * 16 + er;
            const int  col = (int)blockN + wn * 32 + n8 * 8 + ec;
            float v0 = acc[mi][n8][0], v1 = acc[mi][n8][1];
            float v2 = acc[mi][n8][2], v3 = acc[mi][n8][3];
            if (EPI == 2) {
                const float br = bias[row], br8 = bias[row + 8];
                v0 += br; v1 += br; v2 += br8; v3 += br8;
                v0 = (v0 > 20.f) ? v0 : log1pf(expf(v0));
                v1 = (v1 > 20.f) ? v1 : log1pf(expf(v1));
                v2 = (v2 > 20.f) ? v2 : log1pf(expf(v2));
                v3 = (v3 > 20.f) ? v3 : log1pf(expf(v3));
            }
            *(float2*)&Cb[row * ldc + col]       = make_float2(v0, v1);
            *(float2*)&Cb[(row + 8) * ldc + col] = make_float2(v2, v3);
        }
    }
}

// ---------------------------------------------------------------------------
// f32 -> fp16 2-segment split core (row stride 2K).
// ACT==1: [hi | lo].  ACT==0 (weights): [hi | hi].
// ---------------------------------------------------------------------------
__device__ __forceinline__ void split_body(const float* __restrict__ in,
                                           __half* __restrict__ out,
                                           int K, int li, int inRows, int act)
{
    const int e   = li * 4;
    const int row = e / K;
    const int k   = e - row * K;
    float4 v = make_float4(0.f, 0.f, 0.f, 0.f);
    if (row < inRows) v = *(const float4*)(in + (long)row * K + k);
    uint32_t h01, l01, h23, l23;
    cvt_pair(v.x, v.y, h01, l01);
    cvt_pair(v.z, v.w, h23, l23);
    __half* o = out + (long)row * 2 * K + k;
    const uint2 hv = make_uint2(h01, h23);
    *(uint2*)o       = hv;
    *(uint2*)(o + K) = act ? make_uint2(l01, l23) : hv;
}

#define N4_X   (BL * 1024 / 4)
#define N4_WI  (4096 * 1024 / 4)
#define N4_WO  (1024 * 2048 / 4)
#define N4_WX  (128 * 2048 / 4)
#define N4_WDT (2048 * 64 / 4)
__global__ void split_all(const float* __restrict__ x_in,
                          const float* __restrict__ wi_in,
                          const float* __restrict__ wo_in,
                          const float* __restrict__ wx_in,
                          const float* __restrict__ wdt_in,
                          __half* __restrict__ xs,
                          __half* __restrict__ wi,
                          __half* __restrict__ wo,
                          __half* __restrict__ wx,
                          __half* __restrict__ wdt)
{
    int i = blockIdx.x * 256 + threadIdx.x;
    if (i < N4_X) { split_body(x_in, xs, 1024, i, BL, 1); return; }
    i -= N4_X;
    if (i < N4_WI) { split_body(wi_in, wi, 1024, i, 4096, 0); return; }
    i -= N4_WI;
    if (i < N4_WO) { split_body(wo_in, wo, 2048, i, 1024, 0); return; }
    i -= N4_WO;
    if (i < N4_WX) { split_body(wx_in, wx, 2048, i, 96, 0); return; }
    i -= N4_WX;
    if (i < N4_WDT) { split_body(wdt_in, wdt, 64, i, 2048, 0); }
}
#define N4_ALL (N4_X + N4_WI + N4_WO + N4_WX + N4_WDT)

// ---------------------------------------------------------------------------
// Split-K reduce for x_proj partials + dt-row act-split ([hi|lo], row 128)
// ---------------------------------------------------------------------------
__global__ void reduce_split(const float* __restrict__ p,
                             float* __restrict__ xdbl,
                             __half* __restrict__ dtA)
{
    const int n4 = BL * 128 / 4;
    const int i = blockIdx.x * 256 + threadIdx.x;
    if (i >= n4) return;
    float4 a = ((const float4*)p)[i];
#pragma unroll
    for (int s = 1; s < KS; s++) {
        const float4 b = ((const float4*)p)[(long)s * n4 + i];
        a.x += b.x; a.y += b.y; a.z += b.z; a.w += b.w;
    }
    ((float4*)xdbl)[i] = a;
    const int e = i * 4;
    const int col = e & 127;
    if (col < 64) {
        const int row = e >> 7;
        uint32_t h01, l01, h23, l23;
        cvt_pair(a.x, a.y, h01, l01);
        cvt_pair(a.z, a.w, h23, l23);
        __half* o = dtA + (long)row * 128 + col;
        *(uint2*)o        = make_uint2(h01, h23);
        *(uint2*)(o + 64) = make_uint2(l01, l23);
    }
}

// ---------------------------------------------------------------------------
// Depthwise causal conv (k=4) + bias + SiLU in transposed layout, fused with
// [hi|lo] act-split transpose: writes xcT [d][token] f32 AND xcs [token][4096].
// ---------------------------------------------------------------------------
__global__ void conv_split_T(const float* __restrict__ xzT,
                             const float* __restrict__ cw,
                             const float* __restrict__ cb,
                             float* __restrict__ xcT,
                             __half* __restrict__ xcs)
{
    __shared__ float tile[32][33];
    const int d0 = blockIdx.x * 32;
    const int r0 = blockIdx.y * 32;
    const int tx = threadIdx.x;

#pragma unroll
    for (int i = threadIdx.y; i < 32; i += 8) {
        const int d  = d0 + i;
        const int tt = r0 + tx;
        const int l  = tt & (LL - 1);
        const float* row = xzT + ((long)d << 11);
        float acc = cb[d];
#pragma unroll
        for (int k = 0; k < D_CONV; k++) {
            const int ll = l - (D_CONV - 1) + k;
            if (ll >= 0)
                acc = fmaf(row[tt - (D_CONV - 1) + k], cw[d * D_CONV + k], acc);
        }
        const float s = acc / (1.f + __expf(-acc));
        xcT[((long)d << 11) + tt] = s;
        tile[i][tx] = s;
    }
    __syncthreads();
#pragma unroll
    for (int i = threadIdx.y; i < 32; i += 8) {
        const float v = tile[tx][i];
        const int row = r0 + i;
        const int d   = d0 + tx;
        const __half hh = __float2half_rn(v);
        __half* o = xcs + (long)row * 4096 + d;
        o[0]    = hh;
        o[2048] = __float2half_rn(v - __half2float(hh));
    }
}

// ---------------------------------------------------------------------------
// [d][token] f32 -> [token][4096] [hi|lo] split (yT -> ys)
// ---------------------------------------------------------------------------
__global__ void splitT(const float* __restrict__ src,
                       __half* __restrict__ dst)
{
    __shared__ float tile[32][33];
    const int d0 = blockIdx.x * 32;
    const int r0 = blockIdx.y * 32;
#pragma unroll
    for (int i = threadIdx.y; i < 32; i += 8)
        tile[i][threadIdx.x] = src[(long)(d0 + i) * BL + r0 + threadIdx.x];
    __syncthreads();
#pragma unroll
    for (int i = threadIdx.y; i < 32; i += 8) {
        const float v = tile[threadIdx.x][i];
        const int row = r0 + i;
        const int d   = d0 + threadIdx.x;
        const __half hh = __float2half_rn(v);
        __half* o = dst + (long)row * 4096 + d;
        o[0]    = hh;
        o[2048] = __float2half_rn(v - __half2float(hh));
    }
}

// ---------------------------------------------------------------------------
// 3-pass chunked selective scan over transposed operands. NCH=32, CHL=32.
// t = ((b*NCH + c)*D_INNER + d)*16 + n ;  c = (g>>11)&31, b = g>>16
// ---------------------------------------------------------------------------
__global__ void scan_pass_a(const float* __restrict__ dtT,
                            const float* __restrict__ xcT,
                            const float* __restrict__ xdbl,
                            const float* __restrict__ A_log,
                            float* __restrict__ Sarr,
                            float* __restrict__ Parr)
{
    const int t = blockIdx.x * 256 + threadIdx.x;
    const int n = t & 15;
    const int g = t >> 4;
    const int d = g & (D_INNER - 1);
    const int c = (g >> 11) & (NCH - 1);
    const int b = g >> 16;

    const float Aval = -__expf(A_log[d * D_STATE + n]);
    const long base = ((long)d << 11) + (b << 10) + c * CHL;
    const float4* dp4 = (const float4*)(dtT + base);
    const float4* xp4 = (const float4*)(xcT + base);
    const float* xdp  = xdbl + ((long)b * LL + c * CHL) * 128 + 64 + n;

    float h = 0.f, Pr = 1.f;
#pragma unroll
    for (int q = 0; q < CHL / 4; q++) {
        const float4 dl4 = dp4[q];
        const float4 xc4 = xp4[q];
#pragma unroll
        for (int j = 0; j < 4; j++) {
            const float dl  = (j == 0) ? dl4.x : (j == 1) ? dl4.y : (j == 2) ? dl4.z : dl4.w;
            const float xcv = (j == 0) ? xc4.x : (j == 1) ? xc4.y : (j == 2) ? xc4.z : xc4.w;
            const float Bv  = xdp[(q * 4 + j) * 128];
            const float a   = __expf(dl * Aval);
            Pr *= a;
            h = fmaf(a, h, dl * Bv * xcv);
        }
    }
    Sarr[t] = h;
    Parr[t] = Pr;
}

__global__ void scan_pass_b(const float* __restrict__ Sarr,
                            const float* __restrict__ Parr,
                            float* __restrict__ Hc)
{
    const int t = blockIdx.x * 256 + threadIdx.x;
    const int n = t & 15;
    const int d = (t >> 4) & (D_INNER - 1);
    const int b = t >> 15;
    float H = 0.f;
#pragma unroll
    for (int c = 0; c < NCH; c++) {
        const long idx = ((long)((b * NCH + c) * D_INNER + d) << 4) + n;
        Hc[idx] = H;
        H = fmaf(Parr[idx], H, Sarr[idx]);
    }
}

__global__ void scan_pass_c(const float* __restrict__ dtT,
                            const float* __restrict__ xcT,
                            const float* __restrict__ zT,
                            const float* __restrict__ xdbl,
                            const float* __restrict__ A_log,
                            const float* __restrict__ Dv,
                            const float* __restrict__ Hc,
                            float* __restrict__ yT)
{
    const int t = blockIdx.x * 256 + threadIdx.x;
    const int n = t & 15;
    const int g = t >> 4;
    const int d = g & (D_INNER - 1);
    const int c = (g >> 11) & (NCH - 1);
    const int b = g >> 16;

    const float Aval = -__expf(A_log[d * D_STATE + n]);
    const float Dd   = Dv[d];

    const long base = ((long)d << 11) + (b << 10) + c * CHL;
    const float4* dp4 = (const float4*)(dtT + base);
    const float4* xp4 = (const float4*)(xcT + base);
    const float4* zp4 = (const float4*)(zT + base);
    const float* xdp  = xdbl + ((long)b * LL + c * CHL) * 128 + 64 + n;
    float* yp = yT + base;

    float h = Hc[t];
#pragma unroll
    for (int q = 0; q < CHL / 4; q++) {
        const float4 dl4 = dp4[q];
        const float4 xc4 = xp4[q];
        const float4 zv4 = zp4[q];
#pragma unroll
        for (int j = 0; j < 4; j++) {
            const float dl  = (j == 0) ? dl4.x : (j == 1) ? dl4.y : (j == 2) ? dl4.z : dl4.w;
            const float xcv = (j == 0) ? xc4.x : (j == 1) ? xc4.y : (j == 2) ? xc4.z : xc4.w;
            const float zv  = (j == 0) ? zv4.x : (j == 1) ? zv4.y : (j == 2) ? zv4.z : zv4.w;
            const float Bv  = xdp[(q * 4 + j) * 128];
            const float Cv  = xdp[(q * 4 + j) * 128 + 16];

            const float a = __expf(dl * Aval);
            h = fmaf(a, h, dl * Bv * xcv);

            float p = h * Cv;
            p += __shfl_xor_sync(0xffffffffu, p, 8);
            p += __shfl_xor_sync(0xffffffffu, p, 4);
            p += __shfl_xor_sync(0xffffffffu, p, 2);
            p += __shfl_xor_sync(0xffffffffu, p, 1);

            if (n == 0) {
                const float sig = 1.f / (1.f + __expf(-zv));
                yp[q * 4 + j] = (p + xcv * Dd) * (zv * sig);
            }
        }
    }
}

// ---------------------------------------------------------------------------
// out_proj split-K=2 final reduce
// ---------------------------------------------------------------------------
__global__ void reduce_out(const float* __restrict__ p, float* __restrict__ o)
{
    const int n4 = BL * D_MODEL / 4;
    const int i = blockIdx.x * 256 + threadIdx.x;
    if (i >= n4) return;
    const float4 a = ((const float4*)p)[i];
    const float4 b = ((const float4*)p)[n4 + i];
    ((float4*)o)[i] = make_float4(a.x + b.x, a.y + b.y, a.z + b.z, a.w + b.w);
}

// ---------------------------------------------------------------------------
// Launch
// ---------------------------------------------------------------------------
extern "C" void kernel_launch(void* const* d_in, const int* in_sizes, int n_in,
                              void* d_out, int out_size)
{
    const float* x         = (const float*)d_in[0];
    const float* in_proj_w = (const float*)d_in[1];
    const float* conv_w    = (const float*)d_in[2];
    const float* conv_b    = (const float*)d_in[3];
    const float* x_proj_w  = (const float*)d_in[4];
    const float* dt_proj_w = (const float*)d_in[5];
    const float* dt_proj_b = (const float*)d_in[6];
    const float* A_log     = (const float*)d_in[7];
    const float* Dv        = (const float*)d_in[8];
    const float* out_proj  = (const float*)d_in[9];
    float* out = (float*)d_out;

    float *xzT, *xcT, *xpart, *xdbl, *deltaT, *yT, *Sarr, *Parr, *Hc, *opart;
    __half *xcs, *dtA, *ys, *xs, *wi, *wo, *wx, *wdt;
    cudaGetSymbolAddress((void**)&xzT,    g_xzT);
    cudaGetSymbolAddress((void**)&xcT,    g_xcT);
    cudaGetSymbolAddress((void**)&xcs,    g_xcs);
    cudaGetSymbolAddress((void**)&xpart,  g_xpart);
    cudaGetSymbolAddress((void**)&xdbl,   g_xdbl);
    cudaGetSymbolAddress((void**)&dtA,    g_dtA);
    cudaGetSymbolAddress((void**)&deltaT, g_deltaT);
    cudaGetSymbolAddress((void**)&yT,     g_yT);
    cudaGetSymbolAddress((void**)&ys,     g_ys);
    cudaGetSymbolAddress((void**)&xs,     g_xs);
    cudaGetSymbolAddress((void**)&wi,     g_wi);
    cudaGetSymbolAddress((void**)&wo,     g_wo);
    cudaGetSymbolAddress((void**)&wx,     g_wx);
    cudaGetSymbolAddress((void**)&wdt,    g_wdt);
    cudaGetSymbolAddress((void**)&Sarr,   g_S);
    cudaGetSymbolAddress((void**)&Parr,   g_P);
    cudaGetSymbolAddress((void**)&Hc,     g_Hc);
    cudaGetSymbolAddress((void**)&opart,  g_opart);

    const int SMEM_SZ = 6 * 16384;   // 96 KB -> 2 CTAs/SM
    static bool attr_set = false;
    if (!attr_set) {
        cudaFuncSetAttribute(hgemm<0>, cudaFuncAttributeMaxDynamicSharedMemorySize, SMEM_SZ);
        cudaFuncSetAttribute(hgemm<2>, cudaFuncAttributeMaxDynamicSharedMemorySize, SMEM_SZ);
        attr_set = true;
    }

    // launch 0: all operand splits (fp16 [hi|lo] acts, [hi|hi] weights)
    split_all<<<(N4_ALL + 255) / 256, 256>>>(
        x, in_proj_w, out_proj, x_proj_w, dt_proj_w, xs, wi, wo, wx, wdt);

    // launch 1: xzT = in_proj_w @ x.T  (M=4096 ch, N=2048 tok, K'=2048)
    hgemm<0><<<dim3(16, 32, 1), 512, SMEM_SZ>>>(
        wi, xs, xzT, 2048, 2048, BL, 32, 0, nullptr);

    // launch 2: conv + silu + [hi|lo] act-split
    conv_split_T<<<dim3(64, 64), dim3(32, 8)>>>(xzT, conv_w, conv_b, xcT, xcs);

    // launch 3: x_dbl = xc @ x_proj_w.T (K'=4096, split-K=16, T=4)
    hgemm<0><<<dim3(1, 16, KS), 512, SMEM_SZ>>>(
        xcs, wx, xpart, 4096, 4096, 128, 4096 / KS / 64, (long)BL * 128, nullptr);
    // launch 4: reduce + dt [hi|lo] split
    reduce_split<<<(BL * 128 / 4 + 255) / 256, 256>>>(xpart, xdbl, dtA);

    // launch 5: deltaT = softplus(dt_proj_w @ dt.T + b)  (K'=128, T=2)
    hgemm<2><<<dim3(16, 16, 1), 512, SMEM_SZ>>>(
        wdt, dtA, deltaT, 128, 128, BL, 2, 0, dt_proj_b);

    // launch 6-8: 3-pass chunked selective scan (NCH=32)
    scan_pass_a<<<BB * NCH * D_INNER * D_STATE / 256, 256>>>(
        deltaT, xcT, xdbl, A_log, Sarr, Parr);
    scan_pass_b<<<BB * D_INNER * D_STATE / 256, 256>>>(Sarr, Parr, Hc);
    scan_pass_c<<<BB * NCH * D_INNER * D_STATE / 256, 256>>>(
        deltaT, xcT, xzT + (long)2048 * BL, xdbl, A_log, Dv, Hc, yT);

    // launch 9: yT -> ys ([hi|lo] split for out_proj)
    splitT<<<dim3(64, 64), dim3(32, 8)>>>(yT, ys);

    // launch 10-11: out = y @ out_proj_w.T (K'=4096, split-K=2, T=32) + reduce
    hgemm<0><<<dim3(8, 16, 2), 512, SMEM_SZ>>>(
        ys, wo, opart, 4096, 4096, 1024, 32, (long)BL * D_MODEL, nullptr);
    reduce_out<<<(BL * D_MODEL / 4 + 255) / 256, 256>>>(opart, out);
}

// round 16
// speedup vs baseline: 1.8998x; 1.2617x over previous
#include <cuda_runtime.h>
#include <cuda_fp16.h>
#include <math.h>
#include <stdint.h>

// Problem constants
#define D_MODEL 1024
#define D_INNER 2048
#define D_STATE 16
#define DT_RANK 64
#define D_CONV  4
#define BB      2
#define LL      1024
#define BL      (BB * LL)                 // 2048 tokens
#define KS      16                        // split-K for x_proj
#define NCH     32                        // scan chunks per sequence
#define CHL     (LL / NCH)                // 32 steps per chunk

// ---------------------------------------------------------------------------
// Device scratch. Single-term fp16 for in_proj / x_proj / out_proj operands
// (both sides fp16-rounded). dt path stays 2-term: dtA [hi|lo] x wdt [hi|hi]
// (delta feeds exp in the scan -> keep it accurate; also keeps T>=2).
// Transposed dataflow: xzT/xcT/deltaT/yT are [channel][token].
// ---------------------------------------------------------------------------
__device__ float   g_xzT[4096 * BL];
__device__ float   g_xcT[D_INNER * BL];
__device__ __half  g_xch[BL * 2048];        // xc fp16 (x_proj A operand)
__device__ float   g_xpart[KS * BL * 128];
__device__ float   g_xdbl[BL * 128];
__device__ __half  g_dtA[BL * 128];         // dt rows [hi|lo]
__device__ float   g_deltaT[D_INNER * BL];
__device__ float   g_yT[D_INNER * BL];
__device__ __half  g_ys[BL * 2048];         // y fp16 (out_proj A operand)
__device__ __half  g_xs[BL * 1024];         // x fp16
__device__ __half  g_wi[4096 * 1024];
__device__ __half  g_wo[1024 * 2048];
__device__ __half  g_wx[128 * 2048];
__device__ __half  g_wdt[2048 * 128];       // [hi|hi]
// chunked-scan intermediates, t = ((b*NCH+c)*D_INNER+d)*16+n
__device__ float   g_S[BB * NCH * D_INNER * D_STATE];
__device__ float   g_P[BB * NCH * D_INNER * D_STATE];
__device__ float   g_Hc[BB * NCH * D_INNER * D_STATE];
// out_proj split-K partials
__device__ float   g_opart[2 * BL * D_MODEL];

// ---------------------------------------------------------------------------
// helpers
// ---------------------------------------------------------------------------
__device__ __forceinline__ void cvt_pair(float x, float y,
                                         uint32_t& hi, uint32_t& lo) {
    asm("cvt.rn.f16x2.f32 %0, %1, %2;" : "=r"(hi) : "f"(y), "f"(x));
    const __half2 h2 = *reinterpret_cast<const __half2*>(&hi);
    const float hx = __low2float(h2);
    const float hy = __high2float(h2);
    asm("cvt.rn.f16x2.f32 %0, %1, %2;" : "=r"(lo) : "f"(y - hy), "f"(x - hx));
}

__device__ __forceinline__ uint32_t cvt_hi(float x, float y) {
    uint32_t h;
    asm("cvt.rn.f16x2.f32 %0, %1, %2;" : "=r"(h) : "f"(y), "f"(x));
    return h;
}

__device__ __forceinline__ void cp16(uint32_t s, const void* g) {
    asm volatile("cp.async.cg.shared.global [%0], [%1], 16;" :: "r"(s), "l"(g));
}
__device__ __forceinline__ void cp_commit() {
    asm volatile("cp.async.commit_group;");
}
__device__ __forceinline__ void cp_wait1() {
    asm volatile("cp.async.wait_group 1;" ::: "memory");
}

#define LDSM_X4(r0, r1, r2, r3, addr) \
    asm volatile("ldmatrix.sync.aligned.m8n8.x4.shared.b16 {%0,%1,%2,%3}, [%4];" \
                 : "=r"(r0), "=r"(r1), "=r"(r2), "=r"(r3) : "r"(addr))

__device__ __forceinline__ void mma_f16(float (&c)[4],
                                        uint32_t a0, uint32_t a1,
                                        uint32_t a2, uint32_t a3,
                                        uint32_t b0, uint32_t b1) {
    asm volatile(
        "mma.sync.aligned.m16n8k16.row.col.f32.f16.f16.f32 "
        "{%0,%1,%2,%3},{%4,%5,%6,%7},{%8,%9},{%0,%1,%2,%3};"
        : "+f"(c[0]), "+f"(c[1]), "+f"(c[2]), "+f"(c[3])
        : "r"(a0), "r"(a1), "r"(a2), "r"(a3), "r"(b0), "r"(b1));
}

// ---------------------------------------------------------------------------
// fp16 HGEMM, BM=BN=128, BK=64, 512 thr, 3-stage cp.async ring, 2 CTAs/SM.
// EPI==2: +bias[row], softplus (swapped-output GEMMs). Split-K via blockIdx.z.
// Requires M%128==0, N%128==0, K%64==0 per split, T>=2.
// ---------------------------------------------------------------------------
template<int EPI>
__global__ void __launch_bounds__(512, 2)
hgemm(const __half* __restrict__ A, const __half* __restrict__ W,
      float* __restrict__ C, int lda, int ldw, int ldc, int T,
      long czstride, const float* __restrict__ bias)
{
    constexpr int S = 3;
    extern __shared__ __align__(16) char smem[];
    const uint32_t smA0 = (uint32_t)__cvta_generic_to_shared(smem);
    const uint32_t smB0 = smA0 + S * 16384;

    const int tid  = threadIdx.x;
    const int wid  = tid >> 5;
    const int lane = tid & 31;
    const int wm   = wid >> 2;
    const int wn   = wid & 3;
    const int l16  = lane & 15;
    const int chal = lane >> 4;

    const long blockM = (long)blockIdx.y * 128;
    const long blockN = (long)blockIdx.x * 128;
    const int  koff   = blockIdx.z * T * 64;

    const __half* Ab = A + blockM * lda + koff;
    const __half* Wb = W + blockN * ldw + koff;

    const int crow = tid >> 3;
    const int ccc  = tid & 7;

    uint32_t aoff[2], asw[2], boff[2], bsw[2];
#pragma unroll
    for (int mi = 0; mi < 2; mi++) {
        const int r = wm * 32 + mi * 16 + l16;
        aoff[mi] = r * 128;
        asw[mi]  = r & 7;
    }
#pragma unroll
    for (int ni = 0; ni < 2; ni++) {
        const int r = wn * 32 + ni * 16 + l16;
        boff[ni] = r * 128;
        bsw[ni]  = r & 7;
    }

    float acc[2][4][4];
#pragma unroll
    for (int mi = 0; mi < 2; mi++)
#pragma unroll
        for (int n8 = 0; n8 < 4; n8++)
#pragma unroll
            for (int j = 0; j < 4; j++) acc[mi][n8][j] = 0.f;

    auto issue = [&](int s, int t) {
        const int k0 = t * 64;
        const uint32_t dA = smA0 + s * 16384;
        const uint32_t dB = smB0 + s * 16384;
#pragma unroll
        for (int p = 0; p < 2; p++) {
            const int row = crow + p * 64;
            const int scc = ccc ^ (row & 7);
            cp16(dA + row * 128 + scc * 16, Ab + (long)row * lda + k0 + ccc * 8);
            cp16(dB + row * 128 + scc * 16, Wb + (long)row * ldw + k0 + ccc * 8);
        }
    };

    issue(0, 0);
    cp_commit();
    issue(1, 1);
    cp_commit();

    for (int t = 0; t < T; t++) {
        cp_wait1();
        __syncthreads();
        const int nt = t + 2;
        if (nt < T) issue(nt % S, nt);
        cp_commit();

        const uint32_t sA = smA0 + (t % S) * 16384;
        const uint32_t sB = smB0 + (t % S) * 16384;
#pragma unroll
        for (int k16 = 0; k16 < 4; k16++) {
            const uint32_t ch = (uint32_t)(k16 * 2 + chal);
            uint32_t a[2][4], b[2][4];
#pragma unroll
            for (int mi = 0; mi < 2; mi++)
                LDSM_X4(a[mi][0], a[mi][1], a[mi][2], a[mi][3],
                        sA + aoff[mi] + ((ch ^ asw[mi]) << 4));
#pragma unroll
            for (int ni = 0; ni < 2; ni++)
                LDSM_X4(b[ni][0], b[ni][1], b[ni][2], b[ni][3],
                        sB + boff[ni] + ((ch ^ bsw[ni]) << 4));
#pragma unroll
            for (int mi = 0; mi < 2; mi++)
#pragma unroll
                for (int n8 = 0; n8 < 4; n8++) {
                    const int np = n8 >> 1;
                    const uint32_t b0 = (n8 & 1) ? b[np][1] : b[np][0];
                    const uint32_t b1 = (n8 & 1) ? b[np][3] : b[np][2];
                    mma_f16(acc[mi][n8],
                            a[mi][0], a[mi][1], a[mi][2], a[mi][3], b0, b1);
                }
        }
    }

    float* Cb = C + (long)blockIdx.z * czstride;
    const int er = lane >> 2;
    const int ec = (lane & 3) * 2;
#pragma unroll
    for (int mi = 0; mi < 2; mi++) {
#pragma unroll
        for (int n8 = 0; n8 < 4; n8++) {
            const long row = blockM + wm * 32 + mi * 16 + er;
            const int  col = (int)blockN + wn * 32 + n8 * 8 + ec;
            float v0 = acc[mi][n8][0], v1 = acc[mi][n8][1];
            float v2 = acc[mi][n8][2], v3 = acc[mi][n8][3];
            if (EPI == 2) {
                const float br = bias[row], br8 = bias[row + 8];
                v0 += br; v1 += br; v2 += br8; v3 += br8;
                v0 = (v0 > 20.f) ? v0 : log1pf(expf(v0));
                v1 = (v1 > 20.f) ? v1 : log1pf(expf(v1));
                v2 = (v2 > 20.f) ? v2 : log1pf(expf(v2));
                v3 = (v3 > 20.f) ? v3 : log1pf(expf(v3));
            }
            *(float2*)&Cb[row * ldc + col]       = make_float2(v0, v1);
            *(float2*)&Cb[(row + 8) * ldc + col] = make_float2(v2, v3);
        }
    }
}

// ---------------------------------------------------------------------------
// f32 -> fp16 conversion cores.
// mode 0: single fp16, row stride K.
// mode 1: duplicate hi at row stride 2K ([hi|hi], wdt only).
// ---------------------------------------------------------------------------
__device__ __forceinline__ void split_body(const float* __restrict__ in,
                                           __half* __restrict__ out,
                                           int K, int li, int inRows, int dup)
{
    const int e   = li * 4;
    const int row = e / K;
    const int k   = e - row * K;
    float4 v = make_float4(0.f, 0.f, 0.f, 0.f);
    if (row < inRows) v = *(const float4*)(in + (long)row * K + k);
    const uint2 hv = make_uint2(cvt_hi(v.x, v.y), cvt_hi(v.z, v.w));
    if (dup) {
        __half* o = out + (long)row * 2 * K + k;
        *(uint2*)o       = hv;
        *(uint2*)(o + K) = hv;
    } else {
        *(uint2*)(out + (long)row * K + k) = hv;
    }
}

#define N4_X   (BL * 1024 / 4)
#define N4_WI  (4096 * 1024 / 4)
#define N4_WO  (1024 * 2048 / 4)
#define N4_WX  (128 * 2048 / 4)
#define N4_WDT (2048 * 64 / 4)
__global__ void split_all(const float* __restrict__ x_in,
                          const float* __restrict__ wi_in,
                          const float* __restrict__ wo_in,
                          const float* __restrict__ wx_in,
                          const float* __restrict__ wdt_in,
                          __half* __restrict__ xs,
                          __half* __restrict__ wi,
                          __half* __restrict__ wo,
                          __half* __restrict__ wx,
                          __half* __restrict__ wdt)
{
    int i = blockIdx.x * 256 + threadIdx.x;
    if (i < N4_X) { split_body(x_in, xs, 1024, i, BL, 0); return; }
    i -= N4_X;
    if (i < N4_WI) { split_body(wi_in, wi, 1024, i, 4096, 0); return; }
    i -= N4_WI;
    if (i < N4_WO) { split_body(wo_in, wo, 2048, i, 1024, 0); return; }
    i -= N4_WO;
    if (i < N4_WX) { split_body(wx_in, wx, 2048, i, 96, 0); return; }
    i -= N4_WX;
    if (i < N4_WDT) { split_body(wdt_in, wdt, 64, i, 2048, 1); }
}
#define N4_ALL (N4_X + N4_WI + N4_WO + N4_WX + N4_WDT)

// ---------------------------------------------------------------------------
// Split-K reduce for x_proj partials + dt-row [hi|lo] split (row 128)
// ---------------------------------------------------------------------------
__global__ void reduce_split(const float* __restrict__ p,
                             float* __restrict__ xdbl,
                             __half* __restrict__ dtA)
{
    const int n4 = BL * 128 / 4;
    const int i = blockIdx.x * 256 + threadIdx.x;
    if (i >= n4) return;
    float4 a = ((const float4*)p)[i];
#pragma unroll
    for (int s = 1; s < KS; s++) {
        const float4 b = ((const float4*)p)[(long)s * n4 + i];
        a.x += b.x; a.y += b.y; a.z += b.z; a.w += b.w;
    }
    ((float4*)xdbl)[i] = a;
    const int e = i * 4;
    const int col = e & 127;
    if (col < 64) {
        const int row = e >> 7;
        uint32_t h01, l01, h23, l23;
        cvt_pair(a.x, a.y, h01, l01);
        cvt_pair(a.z, a.w, h23, l23);
        __half* o = dtA + (long)row * 128 + col;
        *(uint2*)o        = make_uint2(h01, h23);
        *(uint2*)(o + 64) = make_uint2(l01, l23);
    }
}

// ---------------------------------------------------------------------------
// Depthwise causal conv (k=4) + bias + SiLU in transposed layout, fused with
// fp16 transpose: writes xcT [d][token] f32 AND xch [token][2048] fp16.
// ---------------------------------------------------------------------------
__global__ void conv_split_T(const float* __restrict__ xzT,
                             const float* __restrict__ cw,
                             const float* __restrict__ cb,
                             float* __restrict__ xcT,
                             __half* __restrict__ xch)
{
    __shared__ float tile[32][33];
    const int d0 = blockIdx.x * 32;
    const int r0 = blockIdx.y * 32;
    const int tx = threadIdx.x;

#pragma unroll
    for (int i = threadIdx.y; i < 32; i += 8) {
        const int d  = d0 + i;
        const int tt = r0 + tx;
        const int l  = tt & (LL - 1);
        const float* row = xzT + ((long)d << 11);
        float acc = cb[d];
#pragma unroll
        for (int k = 0; k < D_CONV; k++) {
            const int ll = l - (D_CONV - 1) + k;
            if (ll >= 0)
                acc = fmaf(row[tt - (D_CONV - 1) + k], cw[d * D_CONV + k], acc);
        }
        const float s = acc / (1.f + __expf(-acc));
        xcT[((long)d << 11) + tt] = s;
        tile[i][tx] = s;
    }
    __syncthreads();
#pragma unroll
    for (int i = threadIdx.y; i < 32; i += 8) {
        const float v = tile[tx][i];
        xch[(long)(r0 + i) * 2048 + d0 + tx] = __float2half_rn(v);
    }
}

// ---------------------------------------------------------------------------
// [d][token] f32 -> [token][2048] fp16 (yT -> ys)
// ---------------------------------------------------------------------------
__global__ void splitT(const float* __restrict__ src,
                       __half* __restrict__ dst)
{
    __shared__ float tile[32][33];
    const int d0 = blockIdx.x * 32;
    const int r0 = blockIdx.y * 32;
#pragma unroll
    for (int i = threadIdx.y; i < 32; i += 8)
        tile[i][threadIdx.x] = src[(long)(d0 + i) * BL + r0 + threadIdx.x];
    __syncthreads();
#pragma unroll
    for (int i = threadIdx.y; i < 32; i += 8) {
        const float v = tile[threadIdx.x][i];
        dst[(long)(r0 + i) * 2048 + d0 + threadIdx.x] = __float2half_rn(v);
    }
}

// ---------------------------------------------------------------------------
// 3-pass chunked selective scan over transposed operands. NCH=32, CHL=32.
// t = ((b*NCH + c)*D_INNER + d)*16 + n ;  c = (g>>11)&31, b = g>>16
// ---------------------------------------------------------------------------
__global__ void scan_pass_a(const float* __restrict__ dtT,
                            const float* __restrict__ xcT,
                            const float* __restrict__ xdbl,
                            const float* __restrict__ A_log,
                            float* __restrict__ Sarr,
                            float* __restrict__ Parr)
{
    const int t = blockIdx.x * 256 + threadIdx.x;
    const int n = t & 15;
    const int g = t >> 4;
    const int d = g & (D_INNER - 1);
    const int c = (g >> 11) & (NCH - 1);
    const int b = g >> 16;

    const float Aval = -__expf(A_log[d * D_STATE + n]);
    const long base = ((long)d << 11) + (b << 10) + c * CHL;
    const float4* dp4 = (const float4*)(dtT + base);
    const float4* xp4 = (const float4*)(xcT + base);
    const float* xdp  = xdbl + ((long)b * LL + c * CHL) * 128 + 64 + n;

    float h = 0.f, Pr = 1.f;
#pragma unroll
    for (int q = 0; q < CHL / 4; q++) {
        const float4 dl4 = dp4[q];
        const float4 xc4 = xp4[q];
#pragma unroll
        for (int j = 0; j < 4; j++) {
            const float dl  = (j == 0) ? dl4.x : (j == 1) ? dl4.y : (j == 2) ? dl4.z : dl4.w;
            const float xcv = (j == 0) ? xc4.x : (j == 1) ? xc4.y : (j == 2) ? xc4.z : xc4.w;
            const float Bv  = xdp[(q * 4 + j) * 128];
            const float a   = __expf(dl * Aval);
            Pr *= a;
            h = fmaf(a, h, dl * Bv * xcv);
        }
    }
    Sarr[t] = h;
    Parr[t] = Pr;
}

__global__ void scan_pass_b(const float* __restrict__ Sarr,
                            const float* __restrict__ Parr,
                            float* __restrict__ Hc)
{
    const int t = blockIdx.x * 256 + threadIdx.x;
    const int n = t & 15;
    const int d = (t >> 4) & (D_INNER - 1);
    const int b = t >> 15;
    float H = 0.f;
#pragma unroll
    for (int c = 0; c < NCH; c++) {
        const long idx = ((long)((b * NCH + c) * D_INNER + d) << 4) + n;
        Hc[idx] = H;
        H = fmaf(Parr[idx], H, Sarr[idx]);
    }
}

__global__ void scan_pass_c(const float* __restrict__ dtT,
                            const float* __restrict__ xcT,
                            const float* __restrict__ zT,
                            const float* __restrict__ xdbl,
                            const float* __restrict__ A_log,
                            const float* __restrict__ Dv,
                            const float* __restrict__ Hc,
                            float* __restrict__ yT)
{
    const int t = blockIdx.x * 256 + threadIdx.x;
    const int n = t & 15;
    const int g = t >> 4;
    const int d = g & (D_INNER - 1);
    const int c = (g >> 11) & (NCH - 1);
    const int b = g >> 16;

    const float Aval = -__expf(A_log[d * D_STATE + n]);
    const float Dd   = Dv[d];

    const long base = ((long)d << 11) + (b << 10) + c * CHL;
    const float4* dp4 = (const float4*)(dtT + base);
    const float4* xp4 = (const float4*)(xcT + base);
    const float4* zp4 = (const float4*)(zT + base);
    const float* xdp  = xdbl + ((long)b * LL + c * CHL) * 128 + 64 + n;
    float* yp = yT + base;

    float h = Hc[t];
#pragma unroll
    for (int q = 0; q < CHL / 4; q++) {
        const float4 dl4 = dp4[q];
        const float4 xc4 = xp4[q];
        const float4 zv4 = zp4[q];
#pragma unroll
        for (int j = 0; j < 4; j++) {
            const float dl  = (j == 0) ? dl4.x : (j == 1) ? dl4.y : (j == 2) ? dl4.z : dl4.w;
            const float xcv = (j == 0) ? xc4.x : (j == 1) ? xc4.y : (j == 2) ? xc4.z : xc4.w;
            const float zv  = (j == 0) ? zv4.x : (j == 1) ? zv4.y : (j == 2) ? zv4.z : zv4.w;
            const float Bv  = xdp[(q * 4 + j) * 128];
            const float Cv  = xdp[(q * 4 + j) * 128 + 16];

            const float a = __expf(dl * Aval);
            h = fmaf(a, h, dl * Bv * xcv);

            float p = h * Cv;
            p += __shfl_xor_sync(0xffffffffu, p, 8);
            p += __shfl_xor_sync(0xffffffffu, p, 4);
            p += __shfl_xor_sync(0xffffffffu, p, 2);
            p += __shfl_xor_sync(0xffffffffu, p, 1);

            if (n == 0) {
                const float sig = 1.f / (1.f + __expf(-zv));
                yp[q * 4 + j] = (p + xcv * Dd) * (zv * sig);
            }
        }
    }
}

// ---------------------------------------------------------------------------
// out_proj split-K=2 final reduce
// ---------------------------------------------------------------------------
__global__ void reduce_out(const float* __restrict__ p, float* __restrict__ o)
{
    const int n4 = BL * D_MODEL / 4;
    const int i = blockIdx.x * 256 + threadIdx.x;
    if (i >= n4) return;
    const float4 a = ((const float4*)p)[i];
    const float4 b = ((const float4*)p)[n4 + i];
    ((float4*)o)[i] = make_float4(a.x + b.x, a.y + b.y, a.z + b.z, a.w + b.w);
}

// ---------------------------------------------------------------------------
// Launch
// ---------------------------------------------------------------------------
extern "C" void kernel_launch(void* const* d_in, const int* in_sizes, int n_in,
                              void* d_out, int out_size)
{
    const float* x         = (const float*)d_in[0];
    const float* in_proj_w = (const float*)d_in[1];
    const float* conv_w    = (const float*)d_in[2];
    const float* conv_b    = (const float*)d_in[3];
    const float* x_proj_w  = (const float*)d_in[4];
    const float* dt_proj_w = (const float*)d_in[5];
    const float* dt_proj_b = (const float*)d_in[6];
    const float* A_log     = (const float*)d_in[7];
    const float* Dv        = (const float*)d_in[8];
    const float* out_proj  = (const float*)d_in[9];
    float* out = (float*)d_out;

    float *xzT, *xcT, *xpart, *xdbl, *deltaT, *yT, *Sarr, *Parr, *Hc, *opart;
    __half *xch, *dtA, *ys, *xs, *wi, *wo, *wx, *wdt;
    cudaGetSymbolAddress((void**)&xzT,    g_xzT);
    cudaGetSymbolAddress((void**)&xcT,    g_xcT);
    cudaGetSymbolAddress((void**)&xch,    g_xch);
    cudaGetSymbolAddress((void**)&xpart,  g_xpart);
    cudaGetSymbolAddress((void**)&xdbl,   g_xdbl);
    cudaGetSymbolAddress((void**)&dtA,    g_dtA);
    cudaGetSymbolAddress((void**)&deltaT, g_deltaT);
    cudaGetSymbolAddress((void**)&yT,     g_yT);
    cudaGetSymbolAddress((void**)&ys,     g_ys);
    cudaGetSymbolAddress((void**)&xs,     g_xs);
    cudaGetSymbolAddress((void**)&wi,     g_wi);
    cudaGetSymbolAddress((void**)&wo,     g_wo);
    cudaGetSymbolAddress((void**)&wx,     g_wx);
    cudaGetSymbolAddress((void**)&wdt,    g_wdt);
    cudaGetSymbolAddress((void**)&Sarr,   g_S);
    cudaGetSymbolAddress((void**)&Parr,   g_P);
    cudaGetSymbolAddress((void**)&Hc,     g_Hc);
    cudaGetSymbolAddress((void**)&opart,  g_opart);

    const int SMEM_SZ = 6 * 16384;   // 96 KB -> 2 CTAs/SM
    static bool attr_set = false;
    if (!attr_set) {
        cudaFuncSetAttribute(hgemm<0>, cudaFuncAttributeMaxDynamicSharedMemorySize, SMEM_SZ);
        cudaFuncSetAttribute(hgemm<2>, cudaFuncAttributeMaxDynamicSharedMemorySize, SMEM_SZ);
        attr_set = true;
    }

    // launch 0: all operand conversions (single fp16; wdt duplicated)
    split_all<<<(N4_ALL + 255) / 256, 256>>>(
        x, in_proj_w, out_proj, x_proj_w, dt_proj_w, xs, wi, wo, wx, wdt);

    // launch 1: xzT = in_proj_w @ x.T  (M=4096 ch, N=2048 tok, K=1024, T=16)
    hgemm<0><<<dim3(16, 32, 1), 512, SMEM_SZ>>>(
        wi, xs, xzT, 1024, 1024, BL, 16, 0, nullptr);

    // launch 2: conv + silu (+ fp16 transpose)
    conv_split_T<<<dim3(64, 64), dim3(32, 8)>>>(xzT, conv_w, conv_b, xcT, xch);

    // launch 3: x_dbl = xc @ x_proj_w.T (K=2048, split-K=16, T=2)
    hgemm<0><<<dim3(1, 16, KS), 512, SMEM_SZ>>>(
        xch, wx, xpart, 2048, 2048, 128, 2048 / KS / 64, (long)BL * 128, nullptr);
    // launch 4: reduce + dt [hi|lo] split
    reduce_split<<<(BL * 128 / 4 + 255) / 256, 256>>>(xpart, xdbl, dtA);

    // launch 5: deltaT = softplus(dt_proj_w @ dt.T + b)  (K'=128, T=2; 2-term)
    hgemm<2><<<dim3(16, 16, 1), 512, SMEM_SZ>>>(
        wdt, dtA, deltaT, 128, 128, BL, 2, 0, dt_proj_b);

    // launch 6-8: 3-pass chunked selective scan (NCH=32)
    scan_pass_a<<<BB * NCH * D_INNER * D_STATE / 256, 256>>>(
        deltaT, xcT, xdbl, A_log, Sarr, Parr);
    scan_pass_b<<<BB * D_INNER * D_STATE / 256, 256>>>(Sarr, Parr, Hc);
    scan_pass_c<<<BB * NCH * D_INNER * D_STATE / 256, 256>>>(
        deltaT, xcT, xzT + (long)2048 * BL, xdbl, A_log, Dv, Hc, yT);

    // launch 9: yT -> ys (fp16 for out_proj)
    splitT<<<dim3(64, 64), dim3(32, 8)>>>(yT, ys);

    // launch 10-11: out = y @ out_proj_w.T (K=2048, split-K=2, T=16) + reduce
    hgemm<0><<<dim3(8, 16, 2), 512, SMEM_SZ>>>(
        ys, wo, opart, 2048, 2048, 1024, 16, (long)BL * D_MODEL, nullptr);
    reduce_out<<<(BL * D_MODEL / 4 + 255) / 256, 256>>>(opart, out);
}

// round 17
// speedup vs baseline: 2.0075x; 1.0567x over previous
#include <cuda_runtime.h>
#include <cuda_fp16.h>
#include <math.h>
#include <stdint.h>

// Problem constants
#define D_MODEL 1024
#define D_INNER 2048
#define D_STATE 16
#define DT_RANK 64
#define D_CONV  4
#define BB      2
#define LL      1024
#define BL      (BB * LL)                 // 2048 tokens
#define KS      16                        // split-K for x_proj
#define NCH     32                        // scan chunks per sequence
#define CHL     (LL / NCH)                // 32 steps per chunk

// ---------------------------------------------------------------------------
// Device scratch. Single-term fp16 GEMM operands (in/x/out proj); dt path
// 2-term ([hi|lo] x [hi|hi]). fp16 intermediates xcT/deltaT/yT (write-once,
// read-by-scan). Transposed dataflow: xzT/xcT/deltaT/yT are [channel][token].
// ---------------------------------------------------------------------------
__device__ float   g_xzT[4096 * BL];
__device__ __half  g_xcT[D_INNER * BL];     // conv out fp16 (scan operand)
__device__ __half  g_xch[BL * 2048];        // xc fp16 token-major (x_proj A)
__device__ float   g_xpart[KS * BL * 128];
__device__ float   g_xdbl[BL * 128];
__device__ __half  g_dtA[BL * 128];         // dt rows [hi|lo]
__device__ __half  g_deltaT[D_INNER * BL];  // softplus'd delta fp16
__device__ __half  g_yT[D_INNER * BL];      // scan out fp16
__device__ __half  g_ys[BL * 2048];         // y fp16 token-major (out_proj A)
__device__ __half  g_xs[BL * 1024];
__device__ __half  g_wi[4096 * 1024];
__device__ __half  g_wo[1024 * 2048];
__device__ __half  g_wx[128 * 2048];
__device__ __half  g_wdt[2048 * 128];       // [hi|hi]
// chunked-scan intermediates, t = ((b*NCH+c)*D_INNER+d)*16+n
__device__ float   g_S[BB * NCH * D_INNER * D_STATE];
__device__ float   g_P[BB * NCH * D_INNER * D_STATE];
__device__ float   g_Hc[BB * NCH * D_INNER * D_STATE];

// ---------------------------------------------------------------------------
// helpers
// ---------------------------------------------------------------------------
__device__ __forceinline__ void cvt_pair(float x, float y,
                                         uint32_t& hi, uint32_t& lo) {
    asm("cvt.rn.f16x2.f32 %0, %1, %2;" : "=r"(hi) : "f"(y), "f"(x));
    const __half2 h2 = *reinterpret_cast<const __half2*>(&hi);
    const float hx = __low2float(h2);
    const float hy = __high2float(h2);
    asm("cvt.rn.f16x2.f32 %0, %1, %2;" : "=r"(lo) : "f"(y - hy), "f"(x - hx));
}

__device__ __forceinline__ uint32_t cvt_hi(float x, float y) {
    uint32_t h;
    asm("cvt.rn.f16x2.f32 %0, %1, %2;" : "=r"(h) : "f"(y), "f"(x));
    return h;
}

__device__ __forceinline__ void cp16(uint32_t s, const void* g) {
    asm volatile("cp.async.cg.shared.global [%0], [%1], 16;" :: "r"(s), "l"(g));
}
__device__ __forceinline__ void cp_commit() {
    asm volatile("cp.async.commit_group;");
}
__device__ __forceinline__ void cp_wait1() {
    asm volatile("cp.async.wait_group 1;" ::: "memory");
}

#define LDSM_X4(r0, r1, r2, r3, addr) \
    asm volatile("ldmatrix.sync.aligned.m8n8.x4.shared.b16 {%0,%1,%2,%3}, [%4];" \
                 : "=r"(r0), "=r"(r1), "=r"(r2), "=r"(r3) : "r"(addr))

__device__ __forceinline__ void mma_f16(float (&c)[4],
                                        uint32_t a0, uint32_t a1,
                                        uint32_t a2, uint32_t a3,
                                        uint32_t b0, uint32_t b1) {
    asm volatile(
        "mma.sync.aligned.m16n8k16.row.col.f32.f16.f16.f32 "
        "{%0,%1,%2,%3},{%4,%5,%6,%7},{%8,%9},{%0,%1,%2,%3};"
        : "+f"(c[0]), "+f"(c[1]), "+f"(c[2]), "+f"(c[3])
        : "r"(a0), "r"(a1), "r"(a2), "r"(a3), "r"(b0), "r"(b1));
}

// ---------------------------------------------------------------------------
// fp16 HGEMM, BM=BN=128, BK=64, 512 thr, 3-stage cp.async ring, 2 CTAs/SM.
// EPI==0: f32 store. EPI==2: +bias[row], softplus, fp16 store (dt).
// EPI==4: atomicAdd f32 (out_proj split-K=2; 2-way add is order-exact IEEE,
//         so deterministic). Split-K via blockIdx.z.
// Requires M%128==0, N%128==0, K%64==0 per split, T>=2.
// ---------------------------------------------------------------------------
template<int EPI>
__global__ void __launch_bounds__(512, 2)
hgemm(const __half* __restrict__ A, const __half* __restrict__ W,
      float* __restrict__ C, int lda, int ldw, int ldc, int T,
      long czstride, const float* __restrict__ bias)
{
    constexpr int S = 3;
    extern __shared__ __align__(16) char smem[];
    const uint32_t smA0 = (uint32_t)__cvta_generic_to_shared(smem);
    const uint32_t smB0 = smA0 + S * 16384;

    const int tid  = threadIdx.x;
    const int wid  = tid >> 5;
    const int lane = tid & 31;
    const int wm   = wid >> 2;
    const int wn   = wid & 3;
    const int l16  = lane & 15;
    const int chal = lane >> 4;

    const long blockM = (long)blockIdx.y * 128;
    const long blockN = (long)blockIdx.x * 128;
    const int  koff   = blockIdx.z * T * 64;

    const __half* Ab = A + blockM * lda + koff;
    const __half* Wb = W + blockN * ldw + koff;

    const int crow = tid >> 3;
    const int ccc  = tid & 7;

    uint32_t aoff[2], asw[2], boff[2], bsw[2];
#pragma unroll
    for (int mi = 0; mi < 2; mi++) {
        const int r = wm * 32 + mi * 16 + l16;
        aoff[mi] = r * 128;
        asw[mi]  = r & 7;
    }
#pragma unroll
    for (int ni = 0; ni < 2; ni++) {
        const int r = wn * 32 + ni * 16 + l16;
        boff[ni] = r * 128;
        bsw[ni]  = r & 7;
    }

    float acc[2][4][4];
#pragma unroll
    for (int mi = 0; mi < 2; mi++)
#pragma unroll
        for (int n8 = 0; n8 < 4; n8++)
#pragma unroll
            for (int j = 0; j < 4; j++) acc[mi][n8][j] = 0.f;

    auto issue = [&](int s, int t) {
        const int k0 = t * 64;
        const uint32_t dA = smA0 + s * 16384;
        const uint32_t dB = smB0 + s * 16384;
#pragma unroll
        for (int p = 0; p < 2; p++) {
            const int row = crow + p * 64;
            const int scc = ccc ^ (row & 7);
            cp16(dA + row * 128 + scc * 16, Ab + (long)row * lda + k0 + ccc * 8);
            cp16(dB + row * 128 + scc * 16, Wb + (long)row * ldw + k0 + ccc * 8);
        }
    };

    issue(0, 0);
    cp_commit();
    issue(1, 1);
    cp_commit();

    for (int t = 0; t < T; t++) {
        cp_wait1();
        __syncthreads();
        const int nt = t + 2;
        if (nt < T) issue(nt % S, nt);
        cp_commit();

        const uint32_t sA = smA0 + (t % S) * 16384;
        const uint32_t sB = smB0 + (t % S) * 16384;
#pragma unroll
        for (int k16 = 0; k16 < 4; k16++) {
            const uint32_t ch = (uint32_t)(k16 * 2 + chal);
            uint32_t a[2][4], b[2][4];
#pragma unroll
            for (int mi = 0; mi < 2; mi++)
                LDSM_X4(a[mi][0], a[mi][1], a[mi][2], a[mi][3],
                        sA + aoff[mi] + ((ch ^ asw[mi]) << 4));
#pragma unroll
            for (int ni = 0; ni < 2; ni++)
                LDSM_X4(b[ni][0], b[ni][1], b[ni][2], b[ni][3],
                        sB + boff[ni] + ((ch ^ bsw[ni]) << 4));
#pragma unroll
            for (int mi = 0; mi < 2; mi++)
#pragma unroll
                for (int n8 = 0; n8 < 4; n8++) {
                    const int np = n8 >> 1;
                    const uint32_t b0 = (n8 & 1) ? b[np][1] : b[np][0];
                    const uint32_t b1 = (n8 & 1) ? b[np][3] : b[np][2];
                    mma_f16(acc[mi][n8],
                            a[mi][0], a[mi][1], a[mi][2], a[mi][3], b0, b1);
                }
        }
    }

    float* Cb = C + (long)blockIdx.z * czstride;
    const int er = lane >> 2;
    const int ec = (lane & 3) * 2;
#pragma unroll
    for (int mi = 0; mi < 2; mi++) {
#pragma unroll
        for (int n8 = 0; n8 < 4; n8++) {
            const long row = blockM + wm * 32 + mi * 16 + er;
            const int  col = (int)blockN + wn * 32 + n8 * 8 + ec;
            float v0 = acc[mi][n8][0], v1 = acc[mi][n8][1];
            float v2 = acc[mi][n8][2], v3 = acc[mi][n8][3];
            if (EPI == 2) {
                const float br = bias[row], br8 = bias[row + 8];
                v0 += br; v1 += br; v2 += br8; v3 += br8;
                v0 = (v0 > 20.f) ? v0 : log1pf(expf(v0));
                v1 = (v1 > 20.f) ? v1 : log1pf(expf(v1));
                v2 = (v2 > 20.f) ? v2 : log1pf(expf(v2));
                v3 = (v3 > 20.f) ? v3 : log1pf(expf(v3));
                __half* Ch = (__half*)Cb;
                *(__half2*)&Ch[row * ldc + col]       = __floats2half2_rn(v0, v1);
                *(__half2*)&Ch[(row + 8) * ldc + col] = __floats2half2_rn(v2, v3);
            } else if (EPI == 4) {
                atomicAdd(&Cb[row * ldc + col],           v0);
                atomicAdd(&Cb[row * ldc + col + 1],       v1);
                atomicAdd(&Cb[(row + 8) * ldc + col],     v2);
                atomicAdd(&Cb[(row + 8) * ldc + col + 1], v3);
            } else {
                *(float2*)&Cb[row * ldc + col]       = make_float2(v0, v1);
                *(float2*)&Cb[(row + 8) * ldc + col] = make_float2(v2, v3);
            }
        }
    }
}

// ---------------------------------------------------------------------------
// f32 -> fp16 conversion cores. dup=1: [hi|hi] row stride 2K (wdt only).
// ---------------------------------------------------------------------------
__device__ __forceinline__ void split_body(const float* __restrict__ in,
                                           __half* __restrict__ out,
                                           int K, int li, int inRows, int dup)
{
    const int e   = li * 4;
    const int row = e / K;
    const int k   = e - row * K;
    float4 v = make_float4(0.f, 0.f, 0.f, 0.f);
    if (row < inRows) v = *(const float4*)(in + (long)row * K + k);
    const uint2 hv = make_uint2(cvt_hi(v.x, v.y), cvt_hi(v.z, v.w));
    if (dup) {
        __half* o = out + (long)row * 2 * K + k;
        *(uint2*)o       = hv;
        *(uint2*)(o + K) = hv;
    } else {
        *(uint2*)(out + (long)row * K + k) = hv;
    }
}

#define N4_X   (BL * 1024 / 4)
#define N4_WI  (4096 * 1024 / 4)
#define N4_WO  (1024 * 2048 / 4)
#define N4_WX  (128 * 2048 / 4)
#define N4_WDT (2048 * 64 / 4)
__global__ void split_all(const float* __restrict__ x_in,
                          const float* __restrict__ wi_in,
                          const float* __restrict__ wo_in,
                          const float* __restrict__ wx_in,
                          const float* __restrict__ wdt_in,
                          __half* __restrict__ xs,
                          __half* __restrict__ wi,
                          __half* __restrict__ wo,
                          __half* __restrict__ wx,
                          __half* __restrict__ wdt)
{
    int i = blockIdx.x * 256 + threadIdx.x;
    if (i < N4_X) { split_body(x_in, xs, 1024, i, BL, 0); return; }
    i -= N4_X;
    if (i < N4_WI) { split_body(wi_in, wi, 1024, i, 4096, 0); return; }
    i -= N4_WI;
    if (i < N4_WO) { split_body(wo_in, wo, 2048, i, 1024, 0); return; }
    i -= N4_WO;
    if (i < N4_WX) { split_body(wx_in, wx, 2048, i, 96, 0); return; }
    i -= N4_WX;
    if (i < N4_WDT) { split_body(wdt_in, wdt, 64, i, 2048, 1); }
}
#define N4_ALL (N4_X + N4_WI + N4_WO + N4_WX + N4_WDT)

// ---------------------------------------------------------------------------
// Split-K reduce for x_proj partials + dt-row [hi|lo] split (row 128)
// ---------------------------------------------------------------------------
__global__ void reduce_split(const float* __restrict__ p,
                             float* __restrict__ xdbl,
                             __half* __restrict__ dtA)
{
    const int n4 = BL * 128 / 4;
    const int i = blockIdx.x * 256 + threadIdx.x;
    if (i >= n4) return;
    float4 a = ((const float4*)p)[i];
#pragma unroll
    for (int s = 1; s < KS; s++) {
        const float4 b = ((const float4*)p)[(long)s * n4 + i];
        a.x += b.x; a.y += b.y; a.z += b.z; a.w += b.w;
    }
    ((float4*)xdbl)[i] = a;
    const int e = i * 4;
    const int col = e & 127;
    if (col < 64) {
        const int row = e >> 7;
        uint32_t h01, l01, h23, l23;
        cvt_pair(a.x, a.y, h01, l01);
        cvt_pair(a.z, a.w, h23, l23);
        __half* o = dtA + (long)row * 128 + col;
        *(uint2*)o        = make_uint2(h01, h23);
        *(uint2*)(o + 64) = make_uint2(l01, l23);
    }
}

// ---------------------------------------------------------------------------
// Depthwise causal conv (k=4) + bias + SiLU in transposed layout.
// Writes xcT [d][token] fp16 (scan operand) AND xch [token][2048] fp16.
// ---------------------------------------------------------------------------
__global__ void conv_split_T(const float* __restrict__ xzT,
                             const float* __restrict__ cw,
                             const float* __restrict__ cb,
                             __half* __restrict__ xcT,
                             __half* __restrict__ xch)
{
    __shared__ float tile[32][33];
    const int d0 = blockIdx.x * 32;
    const int r0 = blockIdx.y * 32;
    const int tx = threadIdx.x;

#pragma unroll
    for (int i = threadIdx.y; i < 32; i += 8) {
        const int d  = d0 + i;
        const int tt = r0 + tx;
        const int l  = tt & (LL - 1);
        const float* row = xzT + ((long)d << 11);
        float acc = cb[d];
#pragma unroll
        for (int k = 0; k < D_CONV; k++) {
            const int ll = l - (D_CONV - 1) + k;
            if (ll >= 0)
                acc = fmaf(row[tt - (D_CONV - 1) + k], cw[d * D_CONV + k], acc);
        }
        const float s = acc / (1.f + __expf(-acc));
        xcT[((long)d << 11) + tt] = __float2half_rn(s);
        tile[i][tx] = s;
    }
    __syncthreads();
#pragma unroll
    for (int i = threadIdx.y; i < 32; i += 8) {
        const float v = tile[tx][i];
        xch[(long)(r0 + i) * 2048 + d0 + tx] = __float2half_rn(v);
    }
}

// ---------------------------------------------------------------------------
// yT [d][token] fp16 -> ys [token][2048] fp16 (tiled transpose)
// ---------------------------------------------------------------------------
__global__ void splitT(const __half* __restrict__ src,
                       __half* __restrict__ dst)
{
    __shared__ float tile[32][33];
    const int d0 = blockIdx.x * 32;
    const int r0 = blockIdx.y * 32;
#pragma unroll
    for (int i = threadIdx.y; i < 32; i += 8)
        tile[i][threadIdx.x] = __half2float(src[(long)(d0 + i) * BL + r0 + threadIdx.x]);
    __syncthreads();
#pragma unroll
    for (int i = threadIdx.y; i < 32; i += 8)
        dst[(long)(r0 + i) * 2048 + d0 + threadIdx.x] =
            __float2half_rn(tile[threadIdx.x][i]);
}

// ---------------------------------------------------------------------------
// 3-pass chunked selective scan. NCH=32, CHL=32. dtT/xcT fp16, zT f32.
// t = ((b*NCH + c)*D_INNER + d)*16 + n ;  c = (g>>11)&31, b = g>>16
// ---------------------------------------------------------------------------
__global__ void scan_pass_a(const __half* __restrict__ dtT,
                            const __half* __restrict__ xcT,
                            const float* __restrict__ xdbl,
                            const float* __restrict__ A_log,
                            float* __restrict__ Sarr,
                            float* __restrict__ Parr)
{
    const int t = blockIdx.x * 256 + threadIdx.x;
    const int n = t & 15;
    const int g = t >> 4;
    const int d = g & (D_INNER - 1);
    const int c = (g >> 11) & (NCH - 1);
    const int b = g >> 16;

    const float Aval = -__expf(A_log[d * D_STATE + n]);
    const long base = ((long)d << 11) + (b << 10) + c * CHL;
    const __half2* dp2 = (const __half2*)(dtT + base);
    const __half2* xp2 = (const __half2*)(xcT + base);
    const float* xdp   = xdbl + ((long)b * LL + c * CHL) * 128 + 64 + n;

    float h = 0.f, Pr = 1.f;
#pragma unroll
    for (int q = 0; q < CHL / 2; q++) {
        const __half2 dh = dp2[q];
        const __half2 xh = xp2[q];
        const float dls[2] = {__low2float(dh), __high2float(dh)};
        const float xcs[2] = {__low2float(xh), __high2float(xh)};
#pragma unroll
        for (int j = 0; j < 2; j++) {
            const float Bv = xdp[(q * 2 + j) * 128];
            const float a  = __expf(dls[j] * Aval);
            Pr *= a;
            h = fmaf(a, h, dls[j] * Bv * xcs[j]);
        }
    }
    Sarr[t] = h;
    Parr[t] = Pr;
}

__global__ void scan_pass_b(const float* __restrict__ Sarr,
                            const float* __restrict__ Parr,
                            float* __restrict__ Hc)
{
    const int t = blockIdx.x * 256 + threadIdx.x;
    const int n = t & 15;
    const int d = (t >> 4) & (D_INNER - 1);
    const int b = t >> 15;
    float H = 0.f;
#pragma unroll
    for (int c = 0; c < NCH; c++) {
        const long idx = ((long)((b * NCH + c) * D_INNER + d) << 4) + n;
        Hc[idx] = H;
        H = fmaf(Parr[idx], H, Sarr[idx]);
    }
}

__global__ void scan_pass_c(const __half* __restrict__ dtT,
                            const __half* __restrict__ xcT,
                            const float* __restrict__ zT,
                            const float* __restrict__ xdbl,
                            const float* __restrict__ A_log,
                            const float* __restrict__ Dv,
                            const float* __restrict__ Hc,
                            __half* __restrict__ yT)
{
    const int t = blockIdx.x * 256 + threadIdx.x;
    const int n = t & 15;
    const int g = t >> 4;
    const int d = g & (D_INNER - 1);
    const int c = (g >> 11) & (NCH - 1);
    const int b = g >> 16;

    const float Aval = -__expf(A_log[d * D_STATE + n]);
    const float Dd   = Dv[d];

    const long base = ((long)d << 11) + (b << 10) + c * CHL;
    const __half2* dp2 = (const __half2*)(dtT + base);
    const __half2* xp2 = (const __half2*)(xcT + base);
    const float2* zp2  = (const float2*)(zT + base);
    const float* xdp   = xdbl + ((long)b * LL + c * CHL) * 128 + 64 + n;
    __half* yp = yT + base;

    float h = Hc[t];
#pragma unroll
    for (int q = 0; q < CHL / 2; q++) {
        const __half2 dh = dp2[q];
        const __half2 xh = xp2[q];
        const float2  zv2 = zp2[q];
        const float dls[2] = {__low2float(dh), __high2float(dh)};
        const float xcs[2] = {__low2float(xh), __high2float(xh)};
        const float zvs[2] = {zv2.x, zv2.y};
#pragma unroll
        for (int j = 0; j < 2; j++) {
            const float Bv = xdp[(q * 2 + j) * 128];
            const float Cv = xdp[(q * 2 + j) * 128 + 16];

            const float a = __expf(dls[j] * Aval);
            h = fmaf(a, h, dls[j] * Bv * xcs[j]);

            float p = h * Cv;
            p += __shfl_xor_sync(0xffffffffu, p, 8);
            p += __shfl_xor_sync(0xffffffffu, p, 4);
            p += __shfl_xor_sync(0xffffffffu, p, 2);
            p += __shfl_xor_sync(0xffffffffu, p, 1);

            if (n == 0) {
                const float sig = 1.f / (1.f + __expf(-zvs[j]));
                yp[q * 2 + j] =
                    __float2half_rn((p + xcs[j] * Dd) * (zvs[j] * sig));
            }
        }
    }
}

// ---------------------------------------------------------------------------
// Launch
// ---------------------------------------------------------------------------
extern "C" void kernel_launch(void* const* d_in, const int* in_sizes, int n_in,
                              void* d_out, int out_size)
{
    const float* x         = (const float*)d_in[0];
    const float* in_proj_w = (const float*)d_in[1];
    const float* conv_w    = (const float*)d_in[2];
    const float* conv_b    = (const float*)d_in[3];
    const float* x_proj_w  = (const float*)d_in[4];
    const float* dt_proj_w = (const float*)d_in[5];
    const float* dt_proj_b = (const float*)d_in[6];
    const float* A_log     = (const float*)d_in[7];
    const float* Dv        = (const float*)d_in[8];
    const float* out_proj  = (const float*)d_in[9];
    float* out = (float*)d_out;

    float *xzT, *xpart, *xdbl, *Sarr, *Parr, *Hc;
    __half *xcT, *xch, *dtA, *deltaT, *yT, *ys, *xs, *wi, *wo, *wx, *wdt;
    cudaGetSymbolAddress((void**)&xzT,    g_xzT);
    cudaGetSymbolAddress((void**)&xcT,    g_xcT);
    cudaGetSymbolAddress((void**)&xch,    g_xch);
    cudaGetSymbolAddress((void**)&xpart,  g_xpart);
    cudaGetSymbolAddress((void**)&xdbl,   g_xdbl);
    cudaGetSymbolAddress((void**)&dtA,    g_dtA);
    cudaGetSymbolAddress((void**)&deltaT, g_deltaT);
    cudaGetSymbolAddress((void**)&yT,     g_yT);
    cudaGetSymbolAddress((void**)&ys,     g_ys);
    cudaGetSymbolAddress((void**)&xs,     g_xs);
    cudaGetSymbolAddress((void**)&wi,     g_wi);
    cudaGetSymbolAddress((void**)&wo,     g_wo);
    cudaGetSymbolAddress((void**)&wx,     g_wx);
    cudaGetSymbolAddress((void**)&wdt,    g_wdt);
    cudaGetSymbolAddress((void**)&Sarr,   g_S);
    cudaGetSymbolAddress((void**)&Parr,   g_P);
    cudaGetSymbolAddress((void**)&Hc,     g_Hc);

    const int SMEM_SZ = 6 * 16384;   // 96 KB -> 2 CTAs/SM
    static bool attr_set = false;
    if (!attr_set) {
        cudaFuncSetAttribute(hgemm<0>, cudaFuncAttributeMaxDynamicSharedMemorySize, SMEM_SZ);
        cudaFuncSetAttribute(hgemm<2>, cudaFuncAttributeMaxDynamicSharedMemorySize, SMEM_SZ);
        cudaFuncSetAttribute(hgemm<4>, cudaFuncAttributeMaxDynamicSharedMemorySize, SMEM_SZ);
        attr_set = true;
    }

    // zero d_out for the atomic out_proj epilogue (async, capturable)
    cudaMemsetAsync(out, 0, (size_t)BL * D_MODEL * sizeof(float));

    // operand conversions
    split_all<<<(N4_ALL + 255) / 256, 256>>>(
        x, in_proj_w, out_proj, x_proj_w, dt_proj_w, xs, wi, wo, wx, wdt);

    // xzT = in_proj_w @ x.T  (M=4096 ch, N=2048 tok, K=1024, T=16)
    hgemm<0><<<dim3(16, 32, 1), 512, SMEM_SZ>>>(
        wi, xs, xzT, 1024, 1024, BL, 16, 0, nullptr);

    // conv + silu -> xcT fp16 + xch fp16
    conv_split_T<<<dim3(64, 64), dim3(32, 8)>>>(xzT, conv_w, conv_b, xcT, xch);

    // x_dbl = xc @ x_proj_w.T (K=2048, split-K=16, T=2)
    hgemm<0><<<dim3(1, 16, KS), 512, SMEM_SZ>>>(
        xch, wx, xpart, 2048, 2048, 128, 2048 / KS / 64, (long)BL * 128, nullptr);
    reduce_split<<<(BL * 128 / 4 + 255) / 256, 256>>>(xpart, xdbl, dtA);

    // deltaT = softplus(dt_proj_w @ dt.T + b) -> fp16  (K'=128, T=2; 2-term)
    hgemm<2><<<dim3(16, 16, 1), 512, SMEM_SZ>>>(
        wdt, dtA, (float*)deltaT, 128, 128, BL, 2, 0, dt_proj_b);

    // 3-pass chunked selective scan (NCH=32)
    scan_pass_a<<<BB * NCH * D_INNER * D_STATE / 256, 256>>>(
        deltaT, xcT, xdbl, A_log, Sarr, Parr);
    scan_pass_b<<<BB * D_INNER * D_STATE / 256, 256>>>(Sarr, Parr, Hc);
    scan_pass_c<<<BB * NCH * D_INNER * D_STATE / 256, 256>>>(
        deltaT, xcT, xzT + (long)2048 * BL, xdbl, A_log, Dv, Hc, yT);

    // yT -> ys (fp16 transpose for out_proj)
    splitT<<<dim3(64, 64), dim3(32, 8)>>>(yT, ys);

    // out += y @ out_proj_w.T (K=2048, split-K=2, atomic epilogue)
    hgemm<4><<<dim3(8, 16, 2), 512, SMEM_SZ>>>(
        ys, wo, out, 2048, 2048, 1024, 16, 0, nullptr);
}